// round 2
// baseline (speedup 1.0000x reference)
#include <cuda_runtime.h>
#include <cuda_bf16.h>

// Problem constants
#define BB 8
#define SS 1024
#define DD 1024
#define HH 16
#define HD 64
#define MROWS (BB*SS)     // 8192

// Scratch (device globals; no allocation allowed)
__device__ float g_Q[(size_t)BB*HH*SS*HD];
__device__ float g_K[(size_t)BB*HH*SS*HD];
__device__ float g_V[(size_t)BB*HH*SS*HD];
__device__ float g_ctx[(size_t)BB*SS*DD];

// ---------------------------------------------------------------------------
// Tiled fp32 GEMM: Y = X[M,K] @ W[K,N] + bias, with per-mode epilogue.
// MODE 0: store Q in [B,H,S,HD]
// MODE 1: store K' = scale*K + rel[t] in [B,H,S,HD]
// MODE 2: store V in [B,H,S,HD]
// MODE 3: plain store to Y[M,N] (final output projection)
// Tile: BM=BN=128, BK=16. 256 threads, 8x8 accum per thread.
// ---------------------------------------------------------------------------
template<int MODE>
__global__ void __launch_bounds__(256, 2) gemm_k(
    const float* __restrict__ X, const float* __restrict__ W,
    const float* __restrict__ bias, const float* __restrict__ rel,
    float* __restrict__ Y)
{
    __shared__ float Xs[16][132];   // transposed X tile [k][m]
    __shared__ float Ws[16][132];   // W tile [k][n]

    const int tid = threadIdx.x;
    const int tx  = tid & 15;
    const int ty  = tid >> 4;
    const int m0  = blockIdx.y * 128;
    const int n0  = blockIdx.x * 128;

    float acc[8][8];
    #pragma unroll
    for (int i = 0; i < 8; i++)
        #pragma unroll
        for (int j = 0; j < 8; j++) acc[i][j] = 0.f;

    for (int k0 = 0; k0 < DD; k0 += 16) {
        // Load X tile [128 x 16] -> Xs transposed. 512 float4.
        #pragma unroll
        for (int r = 0; r < 2; r++) {
            int idx = tid * 2 + r;       // 0..511
            int row = idx >> 2;          // 0..127
            int kc  = idx & 3;           // 0..3 (float4 within 16)
            float4 v = *(const float4*)(X + (size_t)(m0 + row) * DD + k0 + kc * 4);
            Xs[kc*4+0][row] = v.x;
            Xs[kc*4+1][row] = v.y;
            Xs[kc*4+2][row] = v.z;
            Xs[kc*4+3][row] = v.w;
        }
        // Load W tile [16 x 128]. 512 float4.
        #pragma unroll
        for (int r = 0; r < 2; r++) {
            int idx = tid * 2 + r;       // 0..511
            int kr  = idx >> 5;          // 0..15
            int nc  = idx & 31;          // 0..31
            float4 v = *(const float4*)(W + (size_t)(k0 + kr) * DD + n0 + nc * 4);
            *(float4*)&Ws[kr][nc * 4] = v;
        }
        __syncthreads();

        #pragma unroll
        for (int kk = 0; kk < 16; kk++) {
            float a[8], bb[8];
            #pragma unroll
            for (int i = 0; i < 8; i++) a[i]  = Xs[kk][ty * 8 + i];
            #pragma unroll
            for (int j = 0; j < 8; j++) bb[j] = Ws[kk][tx * 8 + j];
            #pragma unroll
            for (int i = 0; i < 8; i++)
                #pragma unroll
                for (int j = 0; j < 8; j++)
                    acc[i][j] += a[i] * bb[j];
        }
        __syncthreads();
    }

    // Epilogue
    const float scale = 0.125f;   // HD^-0.5
    #pragma unroll
    for (int i = 0; i < 8; i++) {
        int row = m0 + ty * 8 + i;
        int b = row >> 10;           // /S
        int s = row & 1023;          // %S
        #pragma unroll
        for (int j = 0; j < 8; j++) {
            int col = n0 + tx * 8 + j;
            float y = acc[i][j] + bias[col];
            if (MODE == 3) {
                Y[(size_t)row * DD + col] = y;
            } else {
                int h  = col >> 6;   // /HD
                int hd = col & 63;   // %HD
                size_t idx = (((size_t)(b * HH + h) * SS) + s) * HD + hd;
                if (MODE == 0)      Y[idx] = y;
                else if (MODE == 1) Y[idx] = y * scale + rel[s * HD + hd];
                else                Y[idx] = y;
            }
        }
    }
}

// ---------------------------------------------------------------------------
// Flash attention (fp32). One block = (b,h) x 64 query rows. BN=32 keys/iter.
// K' already includes scale and rel-pos bias, so scores = q . k'.
// Threads: 256 as (tx=16, ty=16): each thread owns 4 query rows (ty*4+i),
// 2 key cols (tx*2+j) for scores, and 4 output dims (tx*4+d) for O.
// ---------------------------------------------------------------------------
__global__ void __launch_bounds__(256) attn_kernel(
    const float* __restrict__ Q, const float* __restrict__ Kp,
    const float* __restrict__ V, const int* __restrict__ mask,
    float* __restrict__ ctx)
{
    __shared__ float Qs[64][65];
    __shared__ float Ks[32][65];
    __shared__ float Vs[32][65];
    __shared__ float Ps[64][34];

    const int tid = threadIdx.x;
    const int tx  = tid & 15;
    const int ty  = tid >> 4;
    const int bh  = blockIdx.y;       // 0..127
    const int b   = bh >> 4;
    const int h   = bh & 15;
    const int s0  = blockIdx.x << 6;  // query tile start

    const float* Qb = Q  + (size_t)bh * SS * HD;
    const float* Kb = Kp + (size_t)bh * SS * HD;
    const float* Vb = V  + (size_t)bh * SS * HD;
    const int*   mb = mask + b * SS;

    // Load 64x64 Q tile
    #pragma unroll
    for (int r = 0; r < 4; r++) {
        int idx = r * 256 + tid;      // 0..1023 float4s
        int row = idx >> 4;
        int c   = idx & 15;
        float4 v = *(const float4*)(Qb + (size_t)(s0 + row) * HD + c * 4);
        Qs[row][c*4+0] = v.x; Qs[row][c*4+1] = v.y;
        Qs[row][c*4+2] = v.z; Qs[row][c*4+3] = v.w;
    }

    float m_[4], l_[4], O[4][4];
    #pragma unroll
    for (int i = 0; i < 4; i++) {
        m_[i] = -1e30f; l_[i] = 0.f;
        #pragma unroll
        for (int d = 0; d < 4; d++) O[i][d] = 0.f;
    }
    __syncthreads();

    for (int t0 = 0; t0 < SS; t0 += 32) {
        // Load K',V tiles 32x64
        #pragma unroll
        for (int r = 0; r < 2; r++) {
            int idx = r * 256 + tid;   // 0..511
            int row = idx >> 4;
            int c   = idx & 15;
            float4 kv = *(const float4*)(Kb + (size_t)(t0 + row) * HD + c * 4);
            Ks[row][c*4+0]=kv.x; Ks[row][c*4+1]=kv.y; Ks[row][c*4+2]=kv.z; Ks[row][c*4+3]=kv.w;
            float4 vv = *(const float4*)(Vb + (size_t)(t0 + row) * HD + c * 4);
            Vs[row][c*4+0]=vv.x; Vs[row][c*4+1]=vv.y; Vs[row][c*4+2]=vv.z; Vs[row][c*4+3]=vv.w;
        }
        __syncthreads();

        // scores: [4 rows][2 cols]
        float sc[4][2];
        #pragma unroll
        for (int i = 0; i < 4; i++) { sc[i][0] = 0.f; sc[i][1] = 0.f; }
        #pragma unroll 8
        for (int kk = 0; kk < 64; kk++) {
            float k0v = Ks[tx*2+0][kk];
            float k1v = Ks[tx*2+1][kk];
            #pragma unroll
            for (int i = 0; i < 4; i++) {
                float a = Qs[ty*4+i][kk];
                sc[i][0] += a * k0v;
                sc[i][1] += a * k1v;
            }
        }

        // key-padding mask
        const bool msk0 = (mb[t0 + tx*2 + 0] == 0);
        const bool msk1 = (mb[t0 + tx*2 + 1] == 0);
        #pragma unroll
        for (int i = 0; i < 4; i++) {
            if (msk0) sc[i][0] = -1e30f;
            if (msk1) sc[i][1] = -1e30f;
        }

        // online softmax update (row reductions over 16-lane groups)
        #pragma unroll
        for (int i = 0; i < 4; i++) {
            float tmax = fmaxf(sc[i][0], sc[i][1]);
            #pragma unroll
            for (int off = 8; off > 0; off >>= 1)
                tmax = fmaxf(tmax, __shfl_xor_sync(0xffffffffu, tmax, off, 16));
            float nm = fmaxf(m_[i], tmax);
            float p0 = __expf(sc[i][0] - nm);
            float p1 = __expf(sc[i][1] - nm);
            float rs = p0 + p1;
            #pragma unroll
            for (int off = 8; off > 0; off >>= 1)
                rs += __shfl_xor_sync(0xffffffffu, rs, off, 16);
            float al = __expf(m_[i] - nm);
            l_[i] = l_[i] * al + rs;
            m_[i] = nm;
            #pragma unroll
            for (int d = 0; d < 4; d++) O[i][d] *= al;
            Ps[ty*4+i][tx*2+0] = p0;
            Ps[ty*4+i][tx*2+1] = p1;
        }
        __syncthreads();

        // O += P @ V
        #pragma unroll 8
        for (int j = 0; j < 32; j++) {
            float v0 = Vs[j][tx*4+0];
            float v1 = Vs[j][tx*4+1];
            float v2 = Vs[j][tx*4+2];
            float v3 = Vs[j][tx*4+3];
            #pragma unroll
            for (int i = 0; i < 4; i++) {
                float p = Ps[ty*4+i][j];
                O[i][0] += p * v0; O[i][1] += p * v1;
                O[i][2] += p * v2; O[i][3] += p * v3;
            }
        }
        __syncthreads();
    }

    // write ctx in [B,S,D] layout
    #pragma unroll
    for (int i = 0; i < 4; i++) {
        float inv = 1.0f / l_[i];
        size_t base = ((size_t)b * SS + (s0 + ty*4 + i)) * DD + h * HD + tx * 4;
        ctx[base+0] = O[i][0] * inv;
        ctx[base+1] = O[i][1] * inv;
        ctx[base+2] = O[i][2] * inv;
        ctx[base+3] = O[i][3] * inv;
    }
}

// ---------------------------------------------------------------------------

extern "C" void kernel_launch(void* const* d_in, const int* in_sizes, int n_in,
                              void* d_out, int out_size) {
    const float* x    = (const float*)d_in[0];
    const float* rel  = (const float*)d_in[1];
    const int*   mask = (const int*)  d_in[2];
    const float* Wq   = (const float*)d_in[3];
    const float* bq   = (const float*)d_in[4];
    const float* Wk   = (const float*)d_in[5];
    const float* bk   = (const float*)d_in[6];
    const float* Wv   = (const float*)d_in[7];
    const float* bv   = (const float*)d_in[8];
    const float* Wo   = (const float*)d_in[9];
    const float* bo   = (const float*)d_in[10];
    float* out = (float*)d_out;

    float *dQ, *dK, *dV, *dCtx;
    cudaGetSymbolAddress((void**)&dQ,   g_Q);
    cudaGetSymbolAddress((void**)&dK,   g_K);
    cudaGetSymbolAddress((void**)&dV,   g_V);
    cudaGetSymbolAddress((void**)&dCtx, g_ctx);

    dim3 ggrid(DD / 128, MROWS / 128);   // (8, 64)
    dim3 gblk(256);

    gemm_k<0><<<ggrid, gblk>>>(x, Wq, bq, rel, dQ);
    gemm_k<1><<<ggrid, gblk>>>(x, Wk, bk, rel, dK);
    gemm_k<2><<<ggrid, gblk>>>(x, Wv, bv, rel, dV);

    attn_kernel<<<dim3(SS / 64, BB * HH), 256>>>(dQ, dK, dV, mask, dCtx);

    gemm_k<3><<<ggrid, gblk>>>(dCtx, Wo, bo, rel, out);
}

// round 3
// speedup vs baseline: 1.6705x; 1.6705x over previous
#include <cuda_runtime.h>
#include <cuda_bf16.h>

// Problem constants
#define BB 8
#define SS 1024
#define DD 1024
#define HH 16
#define HD 64
#define MROWS (BB*SS)     // 8192

// Scratch (device globals; no allocation allowed)
__device__ float g_Q[(size_t)BB*HH*SS*HD];
__device__ float g_K[(size_t)BB*HH*SS*HD];
__device__ float g_V[(size_t)BB*HH*SS*HD];
__device__ float g_ctx[(size_t)BB*SS*DD];

__device__ __forceinline__ unsigned f2tf(float f) {
    unsigned u;
    asm("cvt.rna.tf32.f32 %0, %1;" : "=r"(u) : "f"(f));
    return u;
}

// ---------------------------------------------------------------------------
// tf32 tensor-core GEMM: Y = X[M,1024] @ W[1024,1024] + bias, epilogue by MODE.
// MODE 0: store Q in [B,H,S,HD]
// MODE 1: store K' = scale*K + rel[t] in [B,H,S,HD]
// MODE 2: store V in [B,H,S,HD]
// MODE 3: plain store to Y[M,N] (final output projection)
// Tile: BM=BN=128, BK=32. 256 threads = 8 warps, each warp 64x32 via
// 4x4 grid of mma.sync.m16n8k8.tf32.
// ---------------------------------------------------------------------------
template<int MODE>
__global__ void __launch_bounds__(256, 2) gemm_tf32(
    const float* __restrict__ X, const float* __restrict__ W,
    const float* __restrict__ bias, const float* __restrict__ rel,
    float* __restrict__ Y)
{
    __shared__ unsigned Xs[32][133];   // [k][m], stride 133 => conflict-free STS
    __shared__ unsigned Ws[32][132];   // [k][n]

    const int tid  = threadIdx.x;
    const int warp = tid >> 5;
    const int lane = tid & 31;
    const int g    = lane >> 2;   // 0..7
    const int t4   = lane & 3;    // 0..3
    const int wm   = warp & 1;    // 0..1  (64-row half)
    const int wn   = warp >> 1;   // 0..3  (32-col quarter)
    const int m0   = blockIdx.y * 128;
    const int n0   = blockIdx.x * 128;

    float acc[4][4][4];
    #pragma unroll
    for (int mt = 0; mt < 4; mt++)
        #pragma unroll
        for (int nt = 0; nt < 4; nt++)
            #pragma unroll
            for (int r = 0; r < 4; r++) acc[mt][nt][r] = 0.f;

    for (int k0 = 0; k0 < DD; k0 += 32) {
        // X tile [128 rows x 32 k] -> Xs[k][m] (transposed, tf32-converted)
        #pragma unroll
        for (int i = 0; i < 4; i++) {
            int idx = tid + i * 256;      // 0..1023
            int m   = idx >> 3;           // 0..127
            int kc  = idx & 7;            // float4 index within 32
            float4 v = *(const float4*)(X + (size_t)(m0 + m) * DD + k0 + kc * 4);
            Xs[kc*4+0][m] = f2tf(v.x);
            Xs[kc*4+1][m] = f2tf(v.y);
            Xs[kc*4+2][m] = f2tf(v.z);
            Xs[kc*4+3][m] = f2tf(v.w);
        }
        // W tile [32 k x 128 n] -> Ws[k][n]
        #pragma unroll
        for (int i = 0; i < 4; i++) {
            int idx = tid + i * 256;
            int k   = idx >> 5;           // 0..31
            int nc  = idx & 31;           // 0..31 (float4)
            float4 v = *(const float4*)(W + (size_t)(k0 + k) * DD + n0 + nc * 4);
            uint4 u;
            u.x = f2tf(v.x); u.y = f2tf(v.y); u.z = f2tf(v.z); u.w = f2tf(v.w);
            *(uint4*)&Ws[k][nc * 4] = u;
        }
        __syncthreads();

        #pragma unroll
        for (int ks = 0; ks < 4; ks++) {
            const int kb = ks * 8;
            unsigned a[4][4], b[4][2];
            #pragma unroll
            for (int mt = 0; mt < 4; mt++) {
                int mr = wm * 64 + mt * 16;
                a[mt][0] = Xs[kb + t4    ][mr + g];
                a[mt][1] = Xs[kb + t4    ][mr + g + 8];
                a[mt][2] = Xs[kb + t4 + 4][mr + g];
                a[mt][3] = Xs[kb + t4 + 4][mr + g + 8];
            }
            #pragma unroll
            for (int nt = 0; nt < 4; nt++) {
                int nc = wn * 32 + nt * 8;
                b[nt][0] = Ws[kb + t4    ][nc + g];
                b[nt][1] = Ws[kb + t4 + 4][nc + g];
            }
            #pragma unroll
            for (int mt = 0; mt < 4; mt++)
                #pragma unroll
                for (int nt = 0; nt < 4; nt++)
                    asm volatile(
                        "mma.sync.aligned.m16n8k8.row.col.f32.tf32.tf32.f32 "
                        "{%0,%1,%2,%3}, {%4,%5,%6,%7}, {%8,%9}, {%0,%1,%2,%3};"
                        : "+f"(acc[mt][nt][0]), "+f"(acc[mt][nt][1]),
                          "+f"(acc[mt][nt][2]), "+f"(acc[mt][nt][3])
                        : "r"(a[mt][0]), "r"(a[mt][1]), "r"(a[mt][2]), "r"(a[mt][3]),
                          "r"(b[nt][0]), "r"(b[nt][1]));
        }
        __syncthreads();
    }

    // Epilogue
    const float scale = 0.125f;   // HD^-0.5
    #pragma unroll
    for (int mt = 0; mt < 4; mt++) {
        #pragma unroll
        for (int nt = 0; nt < 4; nt++) {
            int row0 = m0 + wm * 64 + mt * 16 + g;
            int col0 = n0 + wn * 32 + nt * 8 + t4 * 2;
            #pragma unroll
            for (int r = 0; r < 4; r++) {
                int row = row0 + (r >> 1) * 8;
                int col = col0 + (r & 1);
                float y = acc[mt][nt][r] + bias[col];
                if (MODE == 3) {
                    Y[(size_t)row * DD + col] = y;
                } else {
                    int b_  = row >> 10;
                    int s   = row & 1023;
                    int h   = col >> 6;
                    int hd  = col & 63;
                    size_t idx = (((size_t)(b_ * HH + h) * SS) + s) * HD + hd;
                    if (MODE == 0)      Y[idx] = y;
                    else if (MODE == 1) Y[idx] = y * scale + rel[s * HD + hd];
                    else                Y[idx] = y;
                }
            }
        }
    }
}

// ---------------------------------------------------------------------------
// Flash attention (fp32). One block = (b,h) x 64 query rows. BN=32 keys/iter.
// K' already includes scale and rel-pos bias, so scores = q . k'.
// ---------------------------------------------------------------------------
__global__ void __launch_bounds__(256) attn_kernel(
    const float* __restrict__ Q, const float* __restrict__ Kp,
    const float* __restrict__ V, const int* __restrict__ mask,
    float* __restrict__ ctx)
{
    __shared__ float Qs[64][65];
    __shared__ float Ks[32][65];
    __shared__ float Vs[32][65];
    __shared__ float Ps[64][34];

    const int tid = threadIdx.x;
    const int tx  = tid & 15;
    const int ty  = tid >> 4;
    const int bh  = blockIdx.y;       // 0..127
    const int b   = bh >> 4;
    const int h   = bh & 15;
    const int s0  = blockIdx.x << 6;  // query tile start

    const float* Qb = Q  + (size_t)bh * SS * HD;
    const float* Kb = Kp + (size_t)bh * SS * HD;
    const float* Vb = V  + (size_t)bh * SS * HD;
    const int*   mb = mask + b * SS;

    #pragma unroll
    for (int r = 0; r < 4; r++) {
        int idx = r * 256 + tid;
        int row = idx >> 4;
        int c   = idx & 15;
        float4 v = *(const float4*)(Qb + (size_t)(s0 + row) * HD + c * 4);
        Qs[row][c*4+0] = v.x; Qs[row][c*4+1] = v.y;
        Qs[row][c*4+2] = v.z; Qs[row][c*4+3] = v.w;
    }

    float m_[4], l_[4], O[4][4];
    #pragma unroll
    for (int i = 0; i < 4; i++) {
        m_[i] = -1e30f; l_[i] = 0.f;
        #pragma unroll
        for (int d = 0; d < 4; d++) O[i][d] = 0.f;
    }
    __syncthreads();

    for (int t0 = 0; t0 < SS; t0 += 32) {
        #pragma unroll
        for (int r = 0; r < 2; r++) {
            int idx = r * 256 + tid;
            int row = idx >> 4;
            int c   = idx & 15;
            float4 kv = *(const float4*)(Kb + (size_t)(t0 + row) * HD + c * 4);
            Ks[row][c*4+0]=kv.x; Ks[row][c*4+1]=kv.y; Ks[row][c*4+2]=kv.z; Ks[row][c*4+3]=kv.w;
            float4 vv = *(const float4*)(Vb + (size_t)(t0 + row) * HD + c * 4);
            Vs[row][c*4+0]=vv.x; Vs[row][c*4+1]=vv.y; Vs[row][c*4+2]=vv.z; Vs[row][c*4+3]=vv.w;
        }
        __syncthreads();

        float sc[4][2];
        #pragma unroll
        for (int i = 0; i < 4; i++) { sc[i][0] = 0.f; sc[i][1] = 0.f; }
        #pragma unroll 8
        for (int kk = 0; kk < 64; kk++) {
            float k0v = Ks[tx*2+0][kk];
            float k1v = Ks[tx*2+1][kk];
            #pragma unroll
            for (int i = 0; i < 4; i++) {
                float a = Qs[ty*4+i][kk];
                sc[i][0] += a * k0v;
                sc[i][1] += a * k1v;
            }
        }

        const bool msk0 = (mb[t0 + tx*2 + 0] == 0);
        const bool msk1 = (mb[t0 + tx*2 + 1] == 0);
        #pragma unroll
        for (int i = 0; i < 4; i++) {
            if (msk0) sc[i][0] = -1e30f;
            if (msk1) sc[i][1] = -1e30f;
        }

        #pragma unroll
        for (int i = 0; i < 4; i++) {
            float tmax = fmaxf(sc[i][0], sc[i][1]);
            #pragma unroll
            for (int off = 8; off > 0; off >>= 1)
                tmax = fmaxf(tmax, __shfl_xor_sync(0xffffffffu, tmax, off, 16));
            float nm = fmaxf(m_[i], tmax);
            float p0 = __expf(sc[i][0] - nm);
            float p1 = __expf(sc[i][1] - nm);
            float rs = p0 + p1;
            #pragma unroll
            for (int off = 8; off > 0; off >>= 1)
                rs += __shfl_xor_sync(0xffffffffu, rs, off, 16);
            float al = __expf(m_[i] - nm);
            l_[i] = l_[i] * al + rs;
            m_[i] = nm;
            #pragma unroll
            for (int d = 0; d < 4; d++) O[i][d] *= al;
            Ps[ty*4+i][tx*2+0] = p0;
            Ps[ty*4+i][tx*2+1] = p1;
        }
        __syncthreads();

        #pragma unroll 8
        for (int j = 0; j < 32; j++) {
            float v0 = Vs[j][tx*4+0];
            float v1 = Vs[j][tx*4+1];
            float v2 = Vs[j][tx*4+2];
            float v3 = Vs[j][tx*4+3];
            #pragma unroll
            for (int i = 0; i < 4; i++) {
                float p = Ps[ty*4+i][j];
                O[i][0] += p * v0; O[i][1] += p * v1;
                O[i][2] += p * v2; O[i][3] += p * v3;
            }
        }
        __syncthreads();
    }

    #pragma unroll
    for (int i = 0; i < 4; i++) {
        float inv = 1.0f / l_[i];
        size_t base = ((size_t)b * SS + (s0 + ty*4 + i)) * DD + h * HD + tx * 4;
        ctx[base+0] = O[i][0] * inv;
        ctx[base+1] = O[i][1] * inv;
        ctx[base+2] = O[i][2] * inv;
        ctx[base+3] = O[i][3] * inv;
    }
}

// ---------------------------------------------------------------------------

extern "C" void kernel_launch(void* const* d_in, const int* in_sizes, int n_in,
                              void* d_out, int out_size) {
    const float* x    = (const float*)d_in[0];
    const float* rel  = (const float*)d_in[1];
    const int*   mask = (const int*)  d_in[2];
    const float* Wq   = (const float*)d_in[3];
    const float* bq   = (const float*)d_in[4];
    const float* Wk   = (const float*)d_in[5];
    const float* bk   = (const float*)d_in[6];
    const float* Wv   = (const float*)d_in[7];
    const float* bv   = (const float*)d_in[8];
    const float* Wo   = (const float*)d_in[9];
    const float* bo   = (const float*)d_in[10];
    float* out = (float*)d_out;

    float *dQ, *dK, *dV, *dCtx;
    cudaGetSymbolAddress((void**)&dQ,   g_Q);
    cudaGetSymbolAddress((void**)&dK,   g_K);
    cudaGetSymbolAddress((void**)&dV,   g_V);
    cudaGetSymbolAddress((void**)&dCtx, g_ctx);

    dim3 ggrid(DD / 128, MROWS / 128);   // (8, 64)
    dim3 gblk(256);

    gemm_tf32<0><<<ggrid, gblk>>>(x, Wq, bq, rel, dQ);
    gemm_tf32<1><<<ggrid, gblk>>>(x, Wk, bk, rel, dK);
    gemm_tf32<2><<<ggrid, gblk>>>(x, Wv, bv, rel, dV);

    attn_kernel<<<dim3(SS / 64, BB * HH), 256>>>(dQ, dK, dV, mask, dCtx);

    gemm_tf32<3><<<ggrid, gblk>>>(dCtx, Wo, bo, rel, out);
}

// round 5
// speedup vs baseline: 3.1363x; 1.8775x over previous
#include <cuda_runtime.h>
#include <cuda_bf16.h>

// Problem constants
#define BB 8
#define SS 1024
#define DD 1024
#define HH 16
#define HD 64
#define MROWS (BB*SS)     // 8192

// Scratch (device globals; no allocation allowed)
__device__ float g_Q[(size_t)BB*HH*SS*HD];
__device__ float g_K[(size_t)BB*HH*SS*HD];
__device__ float g_V[(size_t)BB*HH*SS*HD];
__device__ float g_ctx[(size_t)BB*SS*DD];

__device__ __forceinline__ unsigned f2tf(float f) {
    unsigned u;
    asm("cvt.rna.tf32.f32 %0, %1;" : "=r"(u) : "f"(f));
    return u;
}

__device__ __forceinline__ void mma_tf32(float c[4], const unsigned a[4], const unsigned b[2]) {
    asm volatile(
        "mma.sync.aligned.m16n8k8.row.col.f32.tf32.tf32.f32 "
        "{%0,%1,%2,%3}, {%4,%5,%6,%7}, {%8,%9}, {%0,%1,%2,%3};"
        : "+f"(c[0]), "+f"(c[1]), "+f"(c[2]), "+f"(c[3])
        : "r"(a[0]), "r"(a[1]), "r"(a[2]), "r"(a[3]),
          "r"(b[0]), "r"(b[1]));
}

// ---------------------------------------------------------------------------
// tf32 tensor-core GEMM: Y = X[M,1024] @ W[1024,1024] + bias, epilogue by MODE.
// MODE 0: Q -> [B,H,S,HD]; MODE 1: K' = scale*K + rel -> [B,H,S,HD];
// MODE 2: V -> [B,H,S,HD]; MODE 3: plain [M,N].
// ---------------------------------------------------------------------------
template<int MODE>
__global__ void __launch_bounds__(256, 2) gemm_tf32(
    const float* __restrict__ X, const float* __restrict__ W,
    const float* __restrict__ bias, const float* __restrict__ rel,
    float* __restrict__ Y)
{
    __shared__ unsigned Xs[32][133];   // [k][m]
    __shared__ unsigned Ws[32][132];   // [k][n]

    const int tid  = threadIdx.x;
    const int warp = tid >> 5;
    const int lane = tid & 31;
    const int g    = lane >> 2;
    const int t4   = lane & 3;
    const int wm   = warp & 1;
    const int wn   = warp >> 1;
    const int m0   = blockIdx.y * 128;
    const int n0   = blockIdx.x * 128;

    float acc[4][4][4];
    #pragma unroll
    for (int mt = 0; mt < 4; mt++)
        #pragma unroll
        for (int nt = 0; nt < 4; nt++)
            #pragma unroll
            for (int r = 0; r < 4; r++) acc[mt][nt][r] = 0.f;

    for (int k0 = 0; k0 < DD; k0 += 32) {
        #pragma unroll
        for (int i = 0; i < 4; i++) {
            int idx = tid + i * 256;
            int m   = idx >> 3;
            int kc  = idx & 7;
            float4 v = *(const float4*)(X + (size_t)(m0 + m) * DD + k0 + kc * 4);
            Xs[kc*4+0][m] = f2tf(v.x);
            Xs[kc*4+1][m] = f2tf(v.y);
            Xs[kc*4+2][m] = f2tf(v.z);
            Xs[kc*4+3][m] = f2tf(v.w);
        }
        #pragma unroll
        for (int i = 0; i < 4; i++) {
            int idx = tid + i * 256;
            int k   = idx >> 5;
            int nc  = idx & 31;
            float4 v = *(const float4*)(W + (size_t)(k0 + k) * DD + n0 + nc * 4);
            uint4 u;
            u.x = f2tf(v.x); u.y = f2tf(v.y); u.z = f2tf(v.z); u.w = f2tf(v.w);
            *(uint4*)&Ws[k][nc * 4] = u;
        }
        __syncthreads();

        #pragma unroll
        for (int ks = 0; ks < 4; ks++) {
            const int kb = ks * 8;
            unsigned a[4][4], b[4][2];
            #pragma unroll
            for (int mt = 0; mt < 4; mt++) {
                int mr = wm * 64 + mt * 16;
                a[mt][0] = Xs[kb + t4    ][mr + g];
                a[mt][1] = Xs[kb + t4    ][mr + g + 8];
                a[mt][2] = Xs[kb + t4 + 4][mr + g];
                a[mt][3] = Xs[kb + t4 + 4][mr + g + 8];
            }
            #pragma unroll
            for (int nt = 0; nt < 4; nt++) {
                int nc = wn * 32 + nt * 8;
                b[nt][0] = Ws[kb + t4    ][nc + g];
                b[nt][1] = Ws[kb + t4 + 4][nc + g];
            }
            #pragma unroll
            for (int mt = 0; mt < 4; mt++)
                #pragma unroll
                for (int nt = 0; nt < 4; nt++)
                    mma_tf32(acc[mt][nt], a[mt], b[nt]);
        }
        __syncthreads();
    }

    const float scale = 0.125f;   // HD^-0.5
    #pragma unroll
    for (int mt = 0; mt < 4; mt++) {
        #pragma unroll
        for (int nt = 0; nt < 4; nt++) {
            int row0 = m0 + wm * 64 + mt * 16 + g;
            int col0 = n0 + wn * 32 + nt * 8 + t4 * 2;
            #pragma unroll
            for (int r = 0; r < 4; r++) {
                int row = row0 + (r >> 1) * 8;
                int col = col0 + (r & 1);
                float y = acc[mt][nt][r] + bias[col];
                if (MODE == 3) {
                    Y[(size_t)row * DD + col] = y;
                } else {
                    int b_  = row >> 10;
                    int s   = row & 1023;
                    int h   = col >> 6;
                    int hd  = col & 63;
                    size_t idx = (((size_t)(b_ * HH + h) * SS) + s) * HD + hd;
                    if (MODE == 0)      Y[idx] = y;
                    else if (MODE == 1) Y[idx] = y * scale + rel[s * HD + hd];
                    else                Y[idx] = y;
                }
            }
        }
    }
}

// ---------------------------------------------------------------------------
// Flash attention with tf32 tensor cores.
// Block = 256 threads (8 warps). BM=128 query rows, BN=64 keys/iter, HD=64.
// Warp w owns query rows [s0 + 16w, s0 + 16w + 16).
// K' already folds scale and rel-pos bias; mask applied as additive -1e30.
// ---------------------------------------------------------------------------
struct AttnSmem {
    union {
        unsigned q[128][68];             // Q tile (tf32) for fragment extraction
        struct {
            unsigned k[64][68];          // K' tile (tf32), pad 68: conflict-free B-frag
            unsigned v[64][72];          // V tile  (tf32), pad 72: conflict-free B-frag
        } kv;
    } u;
    float mbias[64];                     // 0 or -1e30 per key in tile
};

__global__ void __launch_bounds__(256, 2) attn_mma(
    const float* __restrict__ Q, const float* __restrict__ Kp,
    const float* __restrict__ V, const int* __restrict__ mask,
    float* __restrict__ ctx)
{
    __shared__ AttnSmem sm;

    const int tid  = threadIdx.x;
    const int warp = tid >> 5;
    const int lane = tid & 31;
    const int g    = lane >> 2;
    const int t4   = lane & 3;
    const int bh   = blockIdx.y;      // 0..127
    const int b    = bh >> 4;
    const int h    = bh & 15;
    const int s0   = blockIdx.x << 7; // 128-row query tile

    const float* Qb = Q  + (size_t)bh * SS * HD;
    const float* Kb = Kp + (size_t)bh * SS * HD;
    const float* Vb = V  + (size_t)bh * SS * HD;
    const int*   mb = mask + b * SS;

    // ---- Load Q tile [128x64] as tf32 into SMEM ----
    #pragma unroll
    for (int i = 0; i < 8; i++) {
        int idx = tid + i * 256;           // 0..2047 float4s
        int row = idx >> 4;
        int c   = idx & 15;
        float4 v = *(const float4*)(Qb + (size_t)(s0 + row) * HD + c * 4);
        sm.u.q[row][c*4+0] = f2tf(v.x);
        sm.u.q[row][c*4+1] = f2tf(v.y);
        sm.u.q[row][c*4+2] = f2tf(v.z);
        sm.u.q[row][c*4+3] = f2tf(v.w);
    }
    __syncthreads();

    // ---- Extract per-warp Q fragments into registers (persistent) ----
    unsigned Qa[8][4];
    {
        const int mr = warp * 16;
        #pragma unroll
        for (int kt = 0; kt < 8; kt++) {
            Qa[kt][0] = sm.u.q[mr + g    ][kt*8 + t4];
            Qa[kt][1] = sm.u.q[mr + g + 8][kt*8 + t4];
            Qa[kt][2] = sm.u.q[mr + g    ][kt*8 + t4 + 4];
            Qa[kt][3] = sm.u.q[mr + g + 8][kt*8 + t4 + 4];
        }
    }
    __syncthreads();   // done with q region before K/V overwrite

    float Oc[8][4];
    #pragma unroll
    for (int nt = 0; nt < 8; nt++)
        #pragma unroll
        for (int r = 0; r < 4; r++) Oc[nt][r] = 0.f;
    float m0r = -1e30f, m1r = -1e30f, l0r = 0.f, l1r = 0.f;

    const int src0 = (lane & ~3) | (t4 >> 1);         // source lane, cols t4
    const int src2 = (lane & ~3) | ((t4 >> 1) + 2);   // source lane, cols t4+4
    const bool selodd = (t4 & 1);

    for (int t0 = 0; t0 < SS; t0 += 64) {
        // ---- Load K'/V tiles [64x64] as tf32, plus mask bias ----
        #pragma unroll
        for (int i = 0; i < 4; i++) {
            int idx = tid + i * 256;       // 0..1023 float4s
            int row = idx >> 4;
            int c   = idx & 15;
            float4 kv = *(const float4*)(Kb + (size_t)(t0 + row) * HD + c * 4);
            sm.u.kv.k[row][c*4+0] = f2tf(kv.x);
            sm.u.kv.k[row][c*4+1] = f2tf(kv.y);
            sm.u.kv.k[row][c*4+2] = f2tf(kv.z);
            sm.u.kv.k[row][c*4+3] = f2tf(kv.w);
            float4 vv = *(const float4*)(Vb + (size_t)(t0 + row) * HD + c * 4);
            sm.u.kv.v[row][c*4+0] = f2tf(vv.x);
            sm.u.kv.v[row][c*4+1] = f2tf(vv.y);
            sm.u.kv.v[row][c*4+2] = f2tf(vv.z);
            sm.u.kv.v[row][c*4+3] = f2tf(vv.w);
        }
        if (tid < 64) sm.mbias[tid] = (mb[t0 + tid] == 0) ? -1e30f : 0.f;
        __syncthreads();

        // ---- S = Q . K'^T  (scores [16 x 64] per warp) ----
        float s[8][4];
        #pragma unroll
        for (int nt = 0; nt < 8; nt++) {
            s[nt][0] = s[nt][1] = s[nt][2] = s[nt][3] = 0.f;
            #pragma unroll
            for (int kt = 0; kt < 8; kt++) {
                unsigned bf[2];
                bf[0] = sm.u.kv.k[nt*8 + g][kt*8 + t4];
                bf[1] = sm.u.kv.k[nt*8 + g][kt*8 + t4 + 4];
                mma_tf32(s[nt], Qa[kt], bf);
            }
            // key-padding mask (additive)
            float mb0 = sm.mbias[nt*8 + 2*t4];
            float mb1 = sm.mbias[nt*8 + 2*t4 + 1];
            s[nt][0] += mb0; s[nt][1] += mb1;
            s[nt][2] += mb0; s[nt][3] += mb1;
        }

        // ---- Online softmax (rows g and g+8) ----
        float mx0 = -1e30f, mx1 = -1e30f;
        #pragma unroll
        for (int nt = 0; nt < 8; nt++) {
            mx0 = fmaxf(mx0, fmaxf(s[nt][0], s[nt][1]));
            mx1 = fmaxf(mx1, fmaxf(s[nt][2], s[nt][3]));
        }
        mx0 = fmaxf(mx0, __shfl_xor_sync(0xffffffffu, mx0, 1));
        mx0 = fmaxf(mx0, __shfl_xor_sync(0xffffffffu, mx0, 2));
        mx1 = fmaxf(mx1, __shfl_xor_sync(0xffffffffu, mx1, 1));
        mx1 = fmaxf(mx1, __shfl_xor_sync(0xffffffffu, mx1, 2));

        float nm0 = fmaxf(m0r, mx0);
        float nm1 = fmaxf(m1r, mx1);
        float al0 = __expf(m0r - nm0);
        float al1 = __expf(m1r - nm1);
        m0r = nm0; m1r = nm1;

        unsigned pu[8][4];
        float rs0 = 0.f, rs1 = 0.f;
        #pragma unroll
        for (int nt = 0; nt < 8; nt++) {
            float p0 = __expf(s[nt][0] - nm0);
            float p1 = __expf(s[nt][1] - nm0);
            float p2 = __expf(s[nt][2] - nm1);
            float p3 = __expf(s[nt][3] - nm1);
            rs0 += p0 + p1;
            rs1 += p2 + p3;
            pu[nt][0] = f2tf(p0);
            pu[nt][1] = f2tf(p1);
            pu[nt][2] = f2tf(p2);
            pu[nt][3] = f2tf(p3);
        }
        rs0 += __shfl_xor_sync(0xffffffffu, rs0, 1);
        rs0 += __shfl_xor_sync(0xffffffffu, rs0, 2);
        rs1 += __shfl_xor_sync(0xffffffffu, rs1, 1);
        rs1 += __shfl_xor_sync(0xffffffffu, rs1, 2);
        l0r = l0r * al0 + rs0;
        l1r = l1r * al1 + rs1;

        // rescale O
        #pragma unroll
        for (int nt = 0; nt < 8; nt++) {
            Oc[nt][0] *= al0; Oc[nt][1] *= al0;
            Oc[nt][2] *= al1; Oc[nt][3] *= al1;
        }

        // ---- O += P @ V : convert P C-frag -> A-frag via shuffles, then mma ----
        #pragma unroll
        for (int kt = 0; kt < 8; kt++) {
            unsigned aP[4];
            unsigned v00 = __shfl_sync(0xffffffffu, pu[kt][0], src0);
            unsigned v01 = __shfl_sync(0xffffffffu, pu[kt][1], src0);
            unsigned v20 = __shfl_sync(0xffffffffu, pu[kt][2], src0);
            unsigned v21 = __shfl_sync(0xffffffffu, pu[kt][3], src0);
            unsigned w00 = __shfl_sync(0xffffffffu, pu[kt][0], src2);
            unsigned w01 = __shfl_sync(0xffffffffu, pu[kt][1], src2);
            unsigned w20 = __shfl_sync(0xffffffffu, pu[kt][2], src2);
            unsigned w21 = __shfl_sync(0xffffffffu, pu[kt][3], src2);
            aP[0] = selodd ? v01 : v00;   // P[g][t4]
            aP[1] = selodd ? v21 : v20;   // P[g+8][t4]
            aP[2] = selodd ? w01 : w00;   // P[g][t4+4]
            aP[3] = selodd ? w21 : w20;   // P[g+8][t4+4]
            #pragma unroll
            for (int nt = 0; nt < 8; nt++) {
                unsigned bf[2];
                bf[0] = sm.u.kv.v[kt*8 + t4    ][nt*8 + g];
                bf[1] = sm.u.kv.v[kt*8 + t4 + 4][nt*8 + g];
                mma_tf32(Oc[nt], aP, bf);
            }
        }
        __syncthreads();
    }

    // ---- Write ctx [B,S,D] ----
    const float inv0 = 1.0f / l0r;
    const float inv1 = 1.0f / l1r;
    const int r0 = s0 + warp * 16 + g;
    #pragma unroll
    for (int nt = 0; nt < 8; nt++) {
        int col = h * 64 + nt * 8 + 2 * t4;
        float2 o0 = make_float2(Oc[nt][0] * inv0, Oc[nt][1] * inv0);
        float2 o1 = make_float2(Oc[nt][2] * inv1, Oc[nt][3] * inv1);
        *(float2*)(ctx + ((size_t)b * SS + r0    ) * DD + col) = o0;
        *(float2*)(ctx + ((size_t)b * SS + r0 + 8) * DD + col) = o1;
    }
}

// ---------------------------------------------------------------------------

extern "C" void kernel_launch(void* const* d_in, const int* in_sizes, int n_in,
                              void* d_out, int out_size) {
    const float* x    = (const float*)d_in[0];
    const float* rel  = (const float*)d_in[1];
    const int*   mask = (const int*)  d_in[2];
    const float* Wq   = (const float*)d_in[3];
    const float* bq   = (const float*)d_in[4];
    const float* Wk   = (const float*)d_in[5];
    const float* bk   = (const float*)d_in[6];
    const float* Wv   = (const float*)d_in[7];
    const float* bv   = (const float*)d_in[8];
    const float* Wo   = (const float*)d_in[9];
    const float* bo   = (const float*)d_in[10];
    float* out = (float*)d_out;

    float *dQ, *dK, *dV, *dCtx;
    cudaGetSymbolAddress((void**)&dQ,   g_Q);
    cudaGetSymbolAddress((void**)&dK,   g_K);
    cudaGetSymbolAddress((void**)&dV,   g_V);
    cudaGetSymbolAddress((void**)&dCtx, g_ctx);

    dim3 ggrid(DD / 128, MROWS / 128);   // (8, 64)
    dim3 gblk(256);

    gemm_tf32<0><<<ggrid, gblk>>>(x, Wq, bq, rel, dQ);
    gemm_tf32<1><<<ggrid, gblk>>>(x, Wk, bk, rel, dK);
    gemm_tf32<2><<<ggrid, gblk>>>(x, Wv, bv, rel, dV);

    attn_mma<<<dim3(SS / 128, BB * HH), 256>>>(dQ, dK, dV, mask, dCtx);

    gemm_tf32<3><<<ggrid, gblk>>>(dCtx, Wo, bo, rel, out);
}

// round 9
// speedup vs baseline: 3.2702x; 1.0427x over previous
#include <cuda_runtime.h>
#include <cuda_bf16.h>

// Problem constants
#define BB 8
#define SS 1024
#define DD 1024
#define HH 16
#define HD 64
#define MROWS (BB*SS)     // 8192

// Scratch (device globals; no allocation allowed)
__device__ float g_Q[(size_t)BB*HH*SS*HD];
__device__ float g_K[(size_t)BB*HH*SS*HD];
__device__ float g_V[(size_t)BB*HH*SS*HD];
__device__ float g_ctx[(size_t)BB*SS*DD];

__device__ __forceinline__ unsigned f2tf(float f) {
    unsigned u;
    asm("cvt.rna.tf32.f32 %0, %1;" : "=r"(u) : "f"(f));
    return u;
}

__device__ __forceinline__ void mma_tf32(float c[4], const unsigned a[4], const unsigned b[2]) {
    asm volatile(
        "mma.sync.aligned.m16n8k8.row.col.f32.tf32.tf32.f32 "
        "{%0,%1,%2,%3}, {%4,%5,%6,%7}, {%8,%9}, {%0,%1,%2,%3};"
        : "+f"(c[0]), "+f"(c[1]), "+f"(c[2]), "+f"(c[3])
        : "r"(a[0]), "r"(a[1]), "r"(a[2]), "r"(a[3]),
          "r"(b[0]), "r"(b[1]));
}

// ---------------------------------------------------------------------------
// Software-pipelined tf32 GEMM body (macro-free via always_inline lambda style)
// Tile: BM=BN=128, BK=32. 256 threads = 8 warps, warp tile 64x32.
// Pipeline: prefetch next k-tile into registers while MMAs run on smem tile.
// ---------------------------------------------------------------------------

// Fused Q/K/V projection: z = blockIdx.z selects weights/bias/epilogue.
// z==0: Q -> [B,H,S,HD]
// z==1: K' = scale*K + rel -> [B,H,S,HD]
// z==2: V -> [B,H,S,HD]
__global__ void __launch_bounds__(256, 2) gemm_qkv(
    const float* __restrict__ X,
    const float* __restrict__ Wq, const float* __restrict__ Wk, const float* __restrict__ Wv,
    const float* __restrict__ bq, const float* __restrict__ bk, const float* __restrict__ bv,
    const float* __restrict__ rel,
    float* __restrict__ Qo, float* __restrict__ Ko, float* __restrict__ Vo)
{
    __shared__ unsigned Xs[32][133];   // [k][m]
    __shared__ unsigned Ws[32][132];   // [k][n]

    const int z = blockIdx.z;
    const float* W    = (z == 0) ? Wq : (z == 1) ? Wk : Wv;
    const float* bias = (z == 0) ? bq : (z == 1) ? bk : bv;
    float*       Y    = (z == 0) ? Qo : (z == 1) ? Ko : Vo;

    const int tid  = threadIdx.x;
    const int warp = tid >> 5;
    const int lane = tid & 31;
    const int g    = lane >> 2;
    const int t4   = lane & 3;
    const int wm   = warp & 1;
    const int wn   = warp >> 1;
    const int m0   = blockIdx.y * 128;
    const int n0   = blockIdx.x * 128;

    // per-thread load coordinates (fixed across k-tiles)
    const int xm[4] = { (tid + 0*256) >> 3, (tid + 1*256) >> 3, (tid + 2*256) >> 3, (tid + 3*256) >> 3 };
    const int xk    = (tid & 7) * 4;           // same for all i since 256 ≡ 0 mod 8
    const int wk[4] = { (tid + 0*256) >> 5, (tid + 1*256) >> 5, (tid + 2*256) >> 5, (tid + 3*256) >> 5 };
    const int wn4   = (tid & 31) * 4;          // same for all i

    float acc[4][4][4];
    #pragma unroll
    for (int mt = 0; mt < 4; mt++)
        #pragma unroll
        for (int nt = 0; nt < 4; nt++)
            #pragma unroll
            for (int r = 0; r < 4; r++) acc[mt][nt][r] = 0.f;

    float4 px[4], pw[4];
    // prefetch tile 0
    #pragma unroll
    for (int i = 0; i < 4; i++) {
        px[i] = *(const float4*)(X + (size_t)(m0 + xm[i]) * DD + 0 + xk);
        pw[i] = *(const float4*)(W + (size_t)(0 + wk[i]) * DD + n0 + wn4);
    }

    for (int k0 = 0; k0 < DD; k0 += 32) {
        // store current tile (convert to tf32)
        #pragma unroll
        for (int i = 0; i < 4; i++) {
            Xs[xk+0][xm[i]] = f2tf(px[i].x);
            Xs[xk+1][xm[i]] = f2tf(px[i].y);
            Xs[xk+2][xm[i]] = f2tf(px[i].z);
            Xs[xk+3][xm[i]] = f2tf(px[i].w);
            uint4 u;
            u.x = f2tf(pw[i].x); u.y = f2tf(pw[i].y);
            u.z = f2tf(pw[i].z); u.w = f2tf(pw[i].w);
            *(uint4*)&Ws[wk[i]][wn4] = u;
        }
        __syncthreads();

        // issue prefetch for next tile (hidden under MMAs)
        if (k0 + 32 < DD) {
            #pragma unroll
            for (int i = 0; i < 4; i++) {
                px[i] = *(const float4*)(X + (size_t)(m0 + xm[i]) * DD + (k0 + 32) + xk);
                pw[i] = *(const float4*)(W + (size_t)(k0 + 32 + wk[i]) * DD + n0 + wn4);
            }
        }

        #pragma unroll
        for (int ks = 0; ks < 4; ks++) {
            const int kb = ks * 8;
            unsigned a[4][4], b[4][2];
            #pragma unroll
            for (int mt = 0; mt < 4; mt++) {
                int mr = wm * 64 + mt * 16;
                a[mt][0] = Xs[kb + t4    ][mr + g];
                a[mt][1] = Xs[kb + t4    ][mr + g + 8];
                a[mt][2] = Xs[kb + t4 + 4][mr + g];
                a[mt][3] = Xs[kb + t4 + 4][mr + g + 8];
            }
            #pragma unroll
            for (int nt = 0; nt < 4; nt++) {
                int nc = wn * 32 + nt * 8;
                b[nt][0] = Ws[kb + t4    ][nc + g];
                b[nt][1] = Ws[kb + t4 + 4][nc + g];
            }
            #pragma unroll
            for (int mt = 0; mt < 4; mt++)
                #pragma unroll
                for (int nt = 0; nt < 4; nt++)
                    mma_tf32(acc[mt][nt], a[mt], b[nt]);
        }
        __syncthreads();
    }

    // Epilogue -> [B,H,S,HD]
    const float scale = 0.125f;   // HD^-0.5
    #pragma unroll
    for (int mt = 0; mt < 4; mt++) {
        #pragma unroll
        for (int nt = 0; nt < 4; nt++) {
            int row0 = m0 + wm * 64 + mt * 16 + g;
            int col0 = n0 + wn * 32 + nt * 8 + t4 * 2;
            #pragma unroll
            for (int r = 0; r < 4; r++) {
                int row = row0 + (r >> 1) * 8;
                int col = col0 + (r & 1);
                float y = acc[mt][nt][r] + bias[col];
                int b_  = row >> 10;
                int s   = row & 1023;
                int h   = col >> 6;
                int hd  = col & 63;
                size_t idx = (((size_t)(b_ * HH + h) * SS) + s) * HD + hd;
                if (z == 1) y = y * scale + rel[s * HD + hd];
                Y[idx] = y;
            }
        }
    }
}

// Output projection: Y[M,N] = X @ Wo + bo (plain store), same pipeline.
__global__ void __launch_bounds__(256, 2) gemm_out(
    const float* __restrict__ X, const float* __restrict__ W,
    const float* __restrict__ bias, float* __restrict__ Y)
{
    __shared__ unsigned Xs[32][133];
    __shared__ unsigned Ws[32][132];

    const int tid  = threadIdx.x;
    const int warp = tid >> 5;
    const int lane = tid & 31;
    const int g    = lane >> 2;
    const int t4   = lane & 3;
    const int wm   = warp & 1;
    const int wn   = warp >> 1;
    const int m0   = blockIdx.y * 128;
    const int n0   = blockIdx.x * 128;

    const int xm[4] = { (tid + 0*256) >> 3, (tid + 1*256) >> 3, (tid + 2*256) >> 3, (tid + 3*256) >> 3 };
    const int xk    = (tid & 7) * 4;
    const int wk[4] = { (tid + 0*256) >> 5, (tid + 1*256) >> 5, (tid + 2*256) >> 5, (tid + 3*256) >> 5 };
    const int wn4   = (tid & 31) * 4;

    float acc[4][4][4];
    #pragma unroll
    for (int mt = 0; mt < 4; mt++)
        #pragma unroll
        for (int nt = 0; nt < 4; nt++)
            #pragma unroll
            for (int r = 0; r < 4; r++) acc[mt][nt][r] = 0.f;

    float4 px[4], pw[4];
    #pragma unroll
    for (int i = 0; i < 4; i++) {
        px[i] = *(const float4*)(X + (size_t)(m0 + xm[i]) * DD + 0 + xk);
        pw[i] = *(const float4*)(W + (size_t)(0 + wk[i]) * DD + n0 + wn4);
    }

    for (int k0 = 0; k0 < DD; k0 += 32) {
        #pragma unroll
        for (int i = 0; i < 4; i++) {
            Xs[xk+0][xm[i]] = f2tf(px[i].x);
            Xs[xk+1][xm[i]] = f2tf(px[i].y);
            Xs[xk+2][xm[i]] = f2tf(px[i].z);
            Xs[xk+3][xm[i]] = f2tf(px[i].w);
            uint4 u;
            u.x = f2tf(pw[i].x); u.y = f2tf(pw[i].y);
            u.z = f2tf(pw[i].z); u.w = f2tf(pw[i].w);
            *(uint4*)&Ws[wk[i]][wn4] = u;
        }
        __syncthreads();

        if (k0 + 32 < DD) {
            #pragma unroll
            for (int i = 0; i < 4; i++) {
                px[i] = *(const float4*)(X + (size_t)(m0 + xm[i]) * DD + (k0 + 32) + xk);
                pw[i] = *(const float4*)(W + (size_t)(k0 + 32 + wk[i]) * DD + n0 + wn4);
            }
        }

        #pragma unroll
        for (int ks = 0; ks < 4; ks++) {
            const int kb = ks * 8;
            unsigned a[4][4], b[4][2];
            #pragma unroll
            for (int mt = 0; mt < 4; mt++) {
                int mr = wm * 64 + mt * 16;
                a[mt][0] = Xs[kb + t4    ][mr + g];
                a[mt][1] = Xs[kb + t4    ][mr + g + 8];
                a[mt][2] = Xs[kb + t4 + 4][mr + g];
                a[mt][3] = Xs[kb + t4 + 4][mr + g + 8];
            }
            #pragma unroll
            for (int nt = 0; nt < 4; nt++) {
                int nc = wn * 32 + nt * 8;
                b[nt][0] = Ws[kb + t4    ][nc + g];
                b[nt][1] = Ws[kb + t4 + 4][nc + g];
            }
            #pragma unroll
            for (int mt = 0; mt < 4; mt++)
                #pragma unroll
                for (int nt = 0; nt < 4; nt++)
                    mma_tf32(acc[mt][nt], a[mt], b[nt]);
        }
        __syncthreads();
    }

    #pragma unroll
    for (int mt = 0; mt < 4; mt++) {
        #pragma unroll
        for (int nt = 0; nt < 4; nt++) {
            int row0 = m0 + wm * 64 + mt * 16 + g;
            int col0 = n0 + wn * 32 + nt * 8 + t4 * 2;
            #pragma unroll
            for (int r = 0; r < 4; r++) {
                int row = row0 + (r >> 1) * 8;
                int col = col0 + (r & 1);
                Y[(size_t)row * DD + col] = acc[mt][nt][r] + bias[col];
            }
        }
    }
}

// ---------------------------------------------------------------------------
// Flash attention with tf32 tensor cores (unchanged from R4).
// ---------------------------------------------------------------------------
struct AttnSmem {
    union {
        unsigned q[128][68];
        struct {
            unsigned k[64][68];
            unsigned v[64][72];
        } kv;
    } u;
    float mbias[64];
};

__global__ void __launch_bounds__(256, 2) attn_mma(
    const float* __restrict__ Q, const float* __restrict__ Kp,
    const float* __restrict__ V, const int* __restrict__ mask,
    float* __restrict__ ctx)
{
    __shared__ AttnSmem sm;

    const int tid  = threadIdx.x;
    const int warp = tid >> 5;
    const int lane = tid & 31;
    const int g    = lane >> 2;
    const int t4   = lane & 3;
    const int bh   = blockIdx.y;
    const int b    = bh >> 4;
    const int h    = bh & 15;
    const int s0   = blockIdx.x << 7;

    const float* Qb = Q  + (size_t)bh * SS * HD;
    const float* Kb = Kp + (size_t)bh * SS * HD;
    const float* Vb = V  + (size_t)bh * SS * HD;
    const int*   mb = mask + b * SS;

    #pragma unroll
    for (int i = 0; i < 8; i++) {
        int idx = tid + i * 256;
        int row = idx >> 4;
        int c   = idx & 15;
        float4 v = *(const float4*)(Qb + (size_t)(s0 + row) * HD + c * 4);
        sm.u.q[row][c*4+0] = f2tf(v.x);
        sm.u.q[row][c*4+1] = f2tf(v.y);
        sm.u.q[row][c*4+2] = f2tf(v.z);
        sm.u.q[row][c*4+3] = f2tf(v.w);
    }
    __syncthreads();

    unsigned Qa[8][4];
    {
        const int mr = warp * 16;
        #pragma unroll
        for (int kt = 0; kt < 8; kt++) {
            Qa[kt][0] = sm.u.q[mr + g    ][kt*8 + t4];
            Qa[kt][1] = sm.u.q[mr + g + 8][kt*8 + t4];
            Qa[kt][2] = sm.u.q[mr + g    ][kt*8 + t4 + 4];
            Qa[kt][3] = sm.u.q[mr + g + 8][kt*8 + t4 + 4];
        }
    }
    __syncthreads();

    float Oc[8][4];
    #pragma unroll
    for (int nt = 0; nt < 8; nt++)
        #pragma unroll
        for (int r = 0; r < 4; r++) Oc[nt][r] = 0.f;
    float m0r = -1e30f, m1r = -1e30f, l0r = 0.f, l1r = 0.f;

    const int src0 = (lane & ~3) | (t4 >> 1);
    const int src2 = (lane & ~3) | ((t4 >> 1) + 2);
    const bool selodd = (t4 & 1);

    for (int t0 = 0; t0 < SS; t0 += 64) {
        #pragma unroll
        for (int i = 0; i < 4; i++) {
            int idx = tid + i * 256;
            int row = idx >> 4;
            int c   = idx & 15;
            float4 kv = *(const float4*)(Kb + (size_t)(t0 + row) * HD + c * 4);
            sm.u.kv.k[row][c*4+0] = f2tf(kv.x);
            sm.u.kv.k[row][c*4+1] = f2tf(kv.y);
            sm.u.kv.k[row][c*4+2] = f2tf(kv.z);
            sm.u.kv.k[row][c*4+3] = f2tf(kv.w);
            float4 vv = *(const float4*)(Vb + (size_t)(t0 + row) * HD + c * 4);
            sm.u.kv.v[row][c*4+0] = f2tf(vv.x);
            sm.u.kv.v[row][c*4+1] = f2tf(vv.y);
            sm.u.kv.v[row][c*4+2] = f2tf(vv.z);
            sm.u.kv.v[row][c*4+3] = f2tf(vv.w);
        }
        if (tid < 64) sm.mbias[tid] = (mb[t0 + tid] == 0) ? -1e30f : 0.f;
        __syncthreads();

        float s[8][4];
        #pragma unroll
        for (int nt = 0; nt < 8; nt++) {
            s[nt][0] = s[nt][1] = s[nt][2] = s[nt][3] = 0.f;
            #pragma unroll
            for (int kt = 0; kt < 8; kt++) {
                unsigned bf[2];
                bf[0] = sm.u.kv.k[nt*8 + g][kt*8 + t4];
                bf[1] = sm.u.kv.k[nt*8 + g][kt*8 + t4 + 4];
                mma_tf32(s[nt], Qa[kt], bf);
            }
            float mb0 = sm.mbias[nt*8 + 2*t4];
            float mb1 = sm.mbias[nt*8 + 2*t4 + 1];
            s[nt][0] += mb0; s[nt][1] += mb1;
            s[nt][2] += mb0; s[nt][3] += mb1;
        }

        float mx0 = -1e30f, mx1 = -1e30f;
        #pragma unroll
        for (int nt = 0; nt < 8; nt++) {
            mx0 = fmaxf(mx0, fmaxf(s[nt][0], s[nt][1]));
            mx1 = fmaxf(mx1, fmaxf(s[nt][2], s[nt][3]));
        }
        mx0 = fmaxf(mx0, __shfl_xor_sync(0xffffffffu, mx0, 1));
        mx0 = fmaxf(mx0, __shfl_xor_sync(0xffffffffu, mx0, 2));
        mx1 = fmaxf(mx1, __shfl_xor_sync(0xffffffffu, mx1, 1));
        mx1 = fmaxf(mx1, __shfl_xor_sync(0xffffffffu, mx1, 2));

        float nm0 = fmaxf(m0r, mx0);
        float nm1 = fmaxf(m1r, mx1);
        float al0 = __expf(m0r - nm0);
        float al1 = __expf(m1r - nm1);
        m0r = nm0; m1r = nm1;

        unsigned pu[8][4];
        float rs0 = 0.f, rs1 = 0.f;
        #pragma unroll
        for (int nt = 0; nt < 8; nt++) {
            float p0 = __expf(s[nt][0] - nm0);
            float p1 = __expf(s[nt][1] - nm0);
            float p2 = __expf(s[nt][2] - nm1);
            float p3 = __expf(s[nt][3] - nm1);
            rs0 += p0 + p1;
            rs1 += p2 + p3;
            pu[nt][0] = f2tf(p0);
            pu[nt][1] = f2tf(p1);
            pu[nt][2] = f2tf(p2);
            pu[nt][3] = f2tf(p3);
        }
        rs0 += __shfl_xor_sync(0xffffffffu, rs0, 1);
        rs0 += __shfl_xor_sync(0xffffffffu, rs0, 2);
        rs1 += __shfl_xor_sync(0xffffffffu, rs1, 1);
        rs1 += __shfl_xor_sync(0xffffffffu, rs1, 2);
        l0r = l0r * al0 + rs0;
        l1r = l1r * al1 + rs1;

        #pragma unroll
        for (int nt = 0; nt < 8; nt++) {
            Oc[nt][0] *= al0; Oc[nt][1] *= al0;
            Oc[nt][2] *= al1; Oc[nt][3] *= al1;
        }

        #pragma unroll
        for (int kt = 0; kt < 8; kt++) {
            unsigned aP[4];
            unsigned v00 = __shfl_sync(0xffffffffu, pu[kt][0], src0);
            unsigned v01 = __shfl_sync(0xffffffffu, pu[kt][1], src0);
            unsigned v20 = __shfl_sync(0xffffffffu, pu[kt][2], src0);
            unsigned v21 = __shfl_sync(0xffffffffu, pu[kt][3], src0);
            unsigned w00 = __shfl_sync(0xffffffffu, pu[kt][0], src2);
            unsigned w01 = __shfl_sync(0xffffffffu, pu[kt][1], src2);
            unsigned w20 = __shfl_sync(0xffffffffu, pu[kt][2], src2);
            unsigned w21 = __shfl_sync(0xffffffffu, pu[kt][3], src2);
            aP[0] = selodd ? v01 : v00;
            aP[1] = selodd ? v21 : v20;
            aP[2] = selodd ? w01 : w00;
            aP[3] = selodd ? w21 : w20;
            #pragma unroll
            for (int nt = 0; nt < 8; nt++) {
                unsigned bf[2];
                bf[0] = sm.u.kv.v[kt*8 + t4    ][nt*8 + g];
                bf[1] = sm.u.kv.v[kt*8 + t4 + 4][nt*8 + g];
                mma_tf32(Oc[nt], aP, bf);
            }
        }
        __syncthreads();
    }

    const float inv0 = 1.0f / l0r;
    const float inv1 = 1.0f / l1r;
    const int r0 = s0 + warp * 16 + g;
    #pragma unroll
    for (int nt = 0; nt < 8; nt++) {
        int col = h * 64 + nt * 8 + 2 * t4;
        float2 o0 = make_float2(Oc[nt][0] * inv0, Oc[nt][1] * inv0);
        float2 o1 = make_float2(Oc[nt][2] * inv1, Oc[nt][3] * inv1);
        *(float2*)(ctx + ((size_t)b * SS + r0    ) * DD + col) = o0;
        *(float2*)(ctx + ((size_t)b * SS + r0 + 8) * DD + col) = o1;
    }
}

// ---------------------------------------------------------------------------

extern "C" void kernel_launch(void* const* d_in, const int* in_sizes, int n_in,
                              void* d_out, int out_size) {
    const float* x    = (const float*)d_in[0];
    const float* rel  = (const float*)d_in[1];
    const int*   mask = (const int*)  d_in[2];
    const float* Wq   = (const float*)d_in[3];
    const float* bq   = (const float*)d_in[4];
    const float* Wk   = (const float*)d_in[5];
    const float* bk   = (const float*)d_in[6];
    const float* Wv   = (const float*)d_in[7];
    const float* bv   = (const float*)d_in[8];
    const float* Wo   = (const float*)d_in[9];
    const float* bo   = (const float*)d_in[10];
    float* out = (float*)d_out;

    float *dQ, *dK, *dV, *dCtx;
    cudaGetSymbolAddress((void**)&dQ,   g_Q);
    cudaGetSymbolAddress((void**)&dK,   g_K);
    cudaGetSymbolAddress((void**)&dV,   g_V);
    cudaGetSymbolAddress((void**)&dCtx, g_ctx);

    gemm_qkv<<<dim3(DD / 128, MROWS / 128, 3), 256>>>(
        x, Wq, Wk, Wv, bq, bk, bv, rel, dQ, dK, dV);

    attn_mma<<<dim3(SS / 128, BB * HH), 256>>>(dQ, dK, dV, mask, dCtx);

    gemm_out<<<dim3(DD / 128, MROWS / 128), 256>>>(dCtx, Wo, bo, out);
}

// round 11
// speedup vs baseline: 3.9111x; 1.1960x over previous
#include <cuda_runtime.h>
#include <cuda_bf16.h>

// Problem constants
#define BB 8
#define SS 1024
#define DD 1024
#define HH 16
#define HD 64
#define MROWS (BB*SS)     // 8192

// Scratch (device globals; no allocation allowed)
__device__ float g_Q[(size_t)BB*HH*SS*HD];
__device__ float g_K[(size_t)BB*HH*SS*HD];
__device__ float g_V[(size_t)BB*HH*SS*HD];
__device__ float g_ctx[(size_t)BB*SS*DD];

__device__ __forceinline__ unsigned f2tf(float f) {
    unsigned u;
    asm("cvt.rna.tf32.f32 %0, %1;" : "=r"(u) : "f"(f));
    return u;
}

__device__ __forceinline__ void mma_tf32(float c[4], const unsigned a[4], const unsigned b[2]) {
    asm volatile(
        "mma.sync.aligned.m16n8k8.row.col.f32.tf32.tf32.f32 "
        "{%0,%1,%2,%3}, {%4,%5,%6,%7}, {%8,%9}, {%0,%1,%2,%3};"
        : "+f"(c[0]), "+f"(c[1]), "+f"(c[2]), "+f"(c[3])
        : "r"(a[0]), "r"(a[1]), "r"(a[2]), "r"(a[3]),
          "r"(b[0]), "r"(b[1]));
}

__device__ __forceinline__ void ldsm_x4(unsigned r[4], unsigned addr) {
    asm volatile(
        "ldmatrix.sync.aligned.m8n8.x4.shared.b16 {%0,%1,%2,%3}, [%4];"
        : "=r"(r[0]), "=r"(r[1]), "=r"(r[2]), "=r"(r[3]) : "r"(addr));
}

// ---------------------------------------------------------------------------
// Shared GEMM body. Tile BM=BN=128, BK=32; 256 threads = 8 warps (warp 64x32).
// Xs stored [m][k] stride 36 -> STS.128 + ldmatrix.x4 A-frags, conflict-free.
// Ws stored [k][n] stride 136 -> STS.128 + conflict-free scalar B-frag LDS.
// Register-prefetch pipeline across k-tiles.
// ---------------------------------------------------------------------------
struct GemmSmem {
    unsigned Xs[128][36];
    unsigned Ws[32][136];
};

__device__ __forceinline__ void gemm_body(
    const float* __restrict__ X, const float* __restrict__ W,
    GemmSmem& sm, float acc[4][4][4], int m0, int n0)
{
    const int tid  = threadIdx.x;
    const int lane = tid & 31;
    const int warp = tid >> 5;
    const int wm   = warp & 1;
    const int wn   = warp >> 1;
    const int t4   = lane & 3;
    const int g    = lane >> 2;

    // load coordinates (per pass i: X row += 32, W row += 8)
    const int xm  = tid >> 3;          // 0..31
    const int xkc = (tid & 7) * 4;     // k float4 offset
    const int wkr = tid >> 5;          // 0..7
    const int wnc = (tid & 31) * 4;    // n float4 offset

    // ldmatrix base addresses (per mt); lanes 0-15 -> rows r, col kb;
    // lanes 16-31 -> rows r, col kb+4.
    unsigned aBase[4];
    {
        unsigned xs_u32 = (unsigned)__cvta_generic_to_shared(&sm.Xs[0][0]);
        #pragma unroll
        for (int mt = 0; mt < 4; mt++) {
            int row  = wm * 64 + mt * 16 + (lane & 15);
            int colw = (lane >> 4) * 4;
            aBase[mt] = xs_u32 + (unsigned)(row * 36 + colw) * 4u;
        }
    }

    float4 px[4], pw[4];
    #pragma unroll
    for (int i = 0; i < 4; i++) {
        px[i] = *(const float4*)(X + (size_t)(m0 + xm + i * 32) * DD + xkc);
        pw[i] = *(const float4*)(W + (size_t)(wkr + i * 8) * DD + n0 + wnc);
    }

    for (int k0 = 0; k0 < DD; k0 += 32) {
        #pragma unroll
        for (int i = 0; i < 4; i++) {
            uint4 ux, uw;
            ux.x = f2tf(px[i].x); ux.y = f2tf(px[i].y);
            ux.z = f2tf(px[i].z); ux.w = f2tf(px[i].w);
            *(uint4*)&sm.Xs[xm + i * 32][xkc] = ux;
            uw.x = f2tf(pw[i].x); uw.y = f2tf(pw[i].y);
            uw.z = f2tf(pw[i].z); uw.w = f2tf(pw[i].w);
            *(uint4*)&sm.Ws[wkr + i * 8][wnc] = uw;
        }
        __syncthreads();

        if (k0 + 32 < DD) {
            #pragma unroll
            for (int i = 0; i < 4; i++) {
                px[i] = *(const float4*)(X + (size_t)(m0 + xm + i * 32) * DD + (k0 + 32) + xkc);
                pw[i] = *(const float4*)(W + (size_t)(k0 + 32 + wkr + i * 8) * DD + n0 + wnc);
            }
        }

        #pragma unroll
        for (int ks = 0; ks < 4; ks++) {
            const int kb = ks * 8;
            unsigned a[4][4], b[4][2];
            #pragma unroll
            for (int mt = 0; mt < 4; mt++)
                ldsm_x4(a[mt], aBase[mt] + (unsigned)(kb * 4));
            #pragma unroll
            for (int nt = 0; nt < 4; nt++) {
                int nc = wn * 32 + nt * 8;
                b[nt][0] = sm.Ws[kb + t4    ][nc + g];
                b[nt][1] = sm.Ws[kb + t4 + 4][nc + g];
            }
            #pragma unroll
            for (int mt = 0; mt < 4; mt++)
                #pragma unroll
                for (int nt = 0; nt < 4; nt++)
                    mma_tf32(acc[mt][nt], a[mt], b[nt]);
        }
        __syncthreads();
    }
}

// Fused Q/K/V projection: z = blockIdx.z selects weights/bias/epilogue.
__global__ void __launch_bounds__(256, 2) gemm_qkv(
    const float* __restrict__ X,
    const float* __restrict__ Wq, const float* __restrict__ Wk, const float* __restrict__ Wv,
    const float* __restrict__ bq, const float* __restrict__ bk, const float* __restrict__ bv,
    const float* __restrict__ rel,
    float* __restrict__ Qo, float* __restrict__ Ko, float* __restrict__ Vo)
{
    __shared__ GemmSmem sm;

    const int z = blockIdx.z;
    const float* W    = (z == 0) ? Wq : (z == 1) ? Wk : Wv;
    const float* bias = (z == 0) ? bq : (z == 1) ? bk : bv;
    float*       Y    = (z == 0) ? Qo : (z == 1) ? Ko : Vo;

    const int tid  = threadIdx.x;
    const int warp = tid >> 5;
    const int lane = tid & 31;
    const int g    = lane >> 2;
    const int t4   = lane & 3;
    const int wm   = warp & 1;
    const int wn   = warp >> 1;
    const int m0   = blockIdx.y * 128;
    const int n0   = blockIdx.x * 128;

    float acc[4][4][4];
    #pragma unroll
    for (int mt = 0; mt < 4; mt++)
        #pragma unroll
        for (int nt = 0; nt < 4; nt++)
            #pragma unroll
            for (int r = 0; r < 4; r++) acc[mt][nt][r] = 0.f;

    gemm_body(X, W, sm, acc, m0, n0);

    const float scale = 0.125f;   // HD^-0.5
    #pragma unroll
    for (int mt = 0; mt < 4; mt++) {
        #pragma unroll
        for (int nt = 0; nt < 4; nt++) {
            int row0 = m0 + wm * 64 + mt * 16 + g;
            int col0 = n0 + wn * 32 + nt * 8 + t4 * 2;
            #pragma unroll
            for (int r = 0; r < 4; r++) {
                int row = row0 + (r >> 1) * 8;
                int col = col0 + (r & 1);
                float y = acc[mt][nt][r] + bias[col];
                int b_  = row >> 10;
                int s   = row & 1023;
                int h   = col >> 6;
                int hd  = col & 63;
                size_t idx = (((size_t)(b_ * HH + h) * SS) + s) * HD + hd;
                if (z == 1) y = y * scale + rel[s * HD + hd];
                Y[idx] = y;
            }
        }
    }
}

// Output projection: Y[M,N] = X @ Wo + bo (plain store).
__global__ void __launch_bounds__(256, 2) gemm_out(
    const float* __restrict__ X, const float* __restrict__ W,
    const float* __restrict__ bias, float* __restrict__ Y)
{
    __shared__ GemmSmem sm;

    const int tid  = threadIdx.x;
    const int warp = tid >> 5;
    const int lane = tid & 31;
    const int g    = lane >> 2;
    const int t4   = lane & 3;
    const int wm   = warp & 1;
    const int wn   = warp >> 1;
    const int m0   = blockIdx.y * 128;
    const int n0   = blockIdx.x * 128;

    float acc[4][4][4];
    #pragma unroll
    for (int mt = 0; mt < 4; mt++)
        #pragma unroll
        for (int nt = 0; nt < 4; nt++)
            #pragma unroll
            for (int r = 0; r < 4; r++) acc[mt][nt][r] = 0.f;

    gemm_body(X, W, sm, acc, m0, n0);

    #pragma unroll
    for (int mt = 0; mt < 4; mt++) {
        #pragma unroll
        for (int nt = 0; nt < 4; nt++) {
            int row0 = m0 + wm * 64 + mt * 16 + g;
            int col0 = n0 + wn * 32 + nt * 8 + t4 * 2;
            #pragma unroll
            for (int r = 0; r < 4; r++) {
                int row = row0 + (r >> 1) * 8;
                int col = col0 + (r & 1);
                Y[(size_t)row * DD + col] = acc[mt][nt][r] + bias[col];
            }
        }
    }
}

// ---------------------------------------------------------------------------
// Flash attention with tf32 tensor cores (unchanged).
// ---------------------------------------------------------------------------
struct AttnSmem {
    union {
        unsigned q[128][68];
        struct {
            unsigned k[64][68];
            unsigned v[64][72];
        } kv;
    } u;
    float mbias[64];
};

__global__ void __launch_bounds__(256, 2) attn_mma(
    const float* __restrict__ Q, const float* __restrict__ Kp,
    const float* __restrict__ V, const int* __restrict__ mask,
    float* __restrict__ ctx)
{
    __shared__ AttnSmem sm;

    const int tid  = threadIdx.x;
    const int warp = tid >> 5;
    const int lane = tid & 31;
    const int g    = lane >> 2;
    const int t4   = lane & 3;
    const int bh   = blockIdx.y;
    const int b    = bh >> 4;
    const int h    = bh & 15;
    const int s0   = blockIdx.x << 7;

    const float* Qb = Q  + (size_t)bh * SS * HD;
    const float* Kb = Kp + (size_t)bh * SS * HD;
    const float* Vb = V  + (size_t)bh * SS * HD;
    const int*   mb = mask + b * SS;

    #pragma unroll
    for (int i = 0; i < 8; i++) {
        int idx = tid + i * 256;
        int row = idx >> 4;
        int c   = idx & 15;
        float4 v = *(const float4*)(Qb + (size_t)(s0 + row) * HD + c * 4);
        sm.u.q[row][c*4+0] = f2tf(v.x);
        sm.u.q[row][c*4+1] = f2tf(v.y);
        sm.u.q[row][c*4+2] = f2tf(v.z);
        sm.u.q[row][c*4+3] = f2tf(v.w);
    }
    __syncthreads();

    unsigned Qa[8][4];
    {
        const int mr = warp * 16;
        #pragma unroll
        for (int kt = 0; kt < 8; kt++) {
            Qa[kt][0] = sm.u.q[mr + g    ][kt*8 + t4];
            Qa[kt][1] = sm.u.q[mr + g + 8][kt*8 + t4];
            Qa[kt][2] = sm.u.q[mr + g    ][kt*8 + t4 + 4];
            Qa[kt][3] = sm.u.q[mr + g + 8][kt*8 + t4 + 4];
        }
    }
    __syncthreads();

    float Oc[8][4];
    #pragma unroll
    for (int nt = 0; nt < 8; nt++)
        #pragma unroll
        for (int r = 0; r < 4; r++) Oc[nt][r] = 0.f;
    float m0r = -1e30f, m1r = -1e30f, l0r = 0.f, l1r = 0.f;

    const int src0 = (lane & ~3) | (t4 >> 1);
    const int src2 = (lane & ~3) | ((t4 >> 1) + 2);
    const bool selodd = (t4 & 1);

    for (int t0 = 0; t0 < SS; t0 += 64) {
        #pragma unroll
        for (int i = 0; i < 4; i++) {
            int idx = tid + i * 256;
            int row = idx >> 4;
            int c   = idx & 15;
            float4 kv = *(const float4*)(Kb + (size_t)(t0 + row) * HD + c * 4);
            sm.u.kv.k[row][c*4+0] = f2tf(kv.x);
            sm.u.kv.k[row][c*4+1] = f2tf(kv.y);
            sm.u.kv.k[row][c*4+2] = f2tf(kv.z);
            sm.u.kv.k[row][c*4+3] = f2tf(kv.w);
            float4 vv = *(const float4*)(Vb + (size_t)(t0 + row) * HD + c * 4);
            sm.u.kv.v[row][c*4+0] = f2tf(vv.x);
            sm.u.kv.v[row][c*4+1] = f2tf(vv.y);
            sm.u.kv.v[row][c*4+2] = f2tf(vv.z);
            sm.u.kv.v[row][c*4+3] = f2tf(vv.w);
        }
        if (tid < 64) sm.mbias[tid] = (mb[t0 + tid] == 0) ? -1e30f : 0.f;
        __syncthreads();

        float s[8][4];
        #pragma unroll
        for (int nt = 0; nt < 8; nt++) {
            s[nt][0] = s[nt][1] = s[nt][2] = s[nt][3] = 0.f;
            #pragma unroll
            for (int kt = 0; kt < 8; kt++) {
                unsigned bf[2];
                bf[0] = sm.u.kv.k[nt*8 + g][kt*8 + t4];
                bf[1] = sm.u.kv.k[nt*8 + g][kt*8 + t4 + 4];
                mma_tf32(s[nt], Qa[kt], bf);
            }
            float mb0 = sm.mbias[nt*8 + 2*t4];
            float mb1 = sm.mbias[nt*8 + 2*t4 + 1];
            s[nt][0] += mb0; s[nt][1] += mb1;
            s[nt][2] += mb0; s[nt][3] += mb1;
        }

        float mx0 = -1e30f, mx1 = -1e30f;
        #pragma unroll
        for (int nt = 0; nt < 8; nt++) {
            mx0 = fmaxf(mx0, fmaxf(s[nt][0], s[nt][1]));
            mx1 = fmaxf(mx1, fmaxf(s[nt][2], s[nt][3]));
        }
        mx0 = fmaxf(mx0, __shfl_xor_sync(0xffffffffu, mx0, 1));
        mx0 = fmaxf(mx0, __shfl_xor_sync(0xffffffffu, mx0, 2));
        mx1 = fmaxf(mx1, __shfl_xor_sync(0xffffffffu, mx1, 1));
        mx1 = fmaxf(mx1, __shfl_xor_sync(0xffffffffu, mx1, 2));

        float nm0 = fmaxf(m0r, mx0);
        float nm1 = fmaxf(m1r, mx1);
        float al0 = __expf(m0r - nm0);
        float al1 = __expf(m1r - nm1);
        m0r = nm0; m1r = nm1;

        unsigned pu[8][4];
        float rs0 = 0.f, rs1 = 0.f;
        #pragma unroll
        for (int nt = 0; nt < 8; nt++) {
            float p0 = __expf(s[nt][0] - nm0);
            float p1 = __expf(s[nt][1] - nm0);
            float p2 = __expf(s[nt][2] - nm1);
            float p3 = __expf(s[nt][3] - nm1);
            rs0 += p0 + p1;
            rs1 += p2 + p3;
            pu[nt][0] = f2tf(p0);
            pu[nt][1] = f2tf(p1);
            pu[nt][2] = f2tf(p2);
            pu[nt][3] = f2tf(p3);
        }
        rs0 += __shfl_xor_sync(0xffffffffu, rs0, 1);
        rs0 += __shfl_xor_sync(0xffffffffu, rs0, 2);
        rs1 += __shfl_xor_sync(0xffffffffu, rs1, 1);
        rs1 += __shfl_xor_sync(0xffffffffu, rs1, 2);
        l0r = l0r * al0 + rs0;
        l1r = l1r * al1 + rs1;

        #pragma unroll
        for (int nt = 0; nt < 8; nt++) {
            Oc[nt][0] *= al0; Oc[nt][1] *= al0;
            Oc[nt][2] *= al1; Oc[nt][3] *= al1;
        }

        #pragma unroll
        for (int kt = 0; kt < 8; kt++) {
            unsigned aP[4];
            unsigned v00 = __shfl_sync(0xffffffffu, pu[kt][0], src0);
            unsigned v01 = __shfl_sync(0xffffffffu, pu[kt][1], src0);
            unsigned v20 = __shfl_sync(0xffffffffu, pu[kt][2], src0);
            unsigned v21 = __shfl_sync(0xffffffffu, pu[kt][3], src0);
            unsigned w00 = __shfl_sync(0xffffffffu, pu[kt][0], src2);
            unsigned w01 = __shfl_sync(0xffffffffu, pu[kt][1], src2);
            unsigned w20 = __shfl_sync(0xffffffffu, pu[kt][2], src2);
            unsigned w21 = __shfl_sync(0xffffffffu, pu[kt][3], src2);
            aP[0] = selodd ? v01 : v00;
            aP[1] = selodd ? v21 : v20;
            aP[2] = selodd ? w01 : w00;
            aP[3] = selodd ? w21 : w20;
            #pragma unroll
            for (int nt = 0; nt < 8; nt++) {
                unsigned bf[2];
                bf[0] = sm.u.kv.v[kt*8 + t4    ][nt*8 + g];
                bf[1] = sm.u.kv.v[kt*8 + t4 + 4][nt*8 + g];
                mma_tf32(Oc[nt], aP, bf);
            }
        }
        __syncthreads();
    }

    const float inv0 = 1.0f / l0r;
    const float inv1 = 1.0f / l1r;
    const int r0 = s0 + warp * 16 + g;
    #pragma unroll
    for (int nt = 0; nt < 8; nt++) {
        int col = h * 64 + nt * 8 + 2 * t4;
        float2 o0 = make_float2(Oc[nt][0] * inv0, Oc[nt][1] * inv0);
        float2 o1 = make_float2(Oc[nt][2] * inv1, Oc[nt][3] * inv1);
        *(float2*)(ctx + ((size_t)b * SS + r0    ) * DD + col) = o0;
        *(float2*)(ctx + ((size_t)b * SS + r0 + 8) * DD + col) = o1;
    }
}

// ---------------------------------------------------------------------------

extern "C" void kernel_launch(void* const* d_in, const int* in_sizes, int n_in,
                              void* d_out, int out_size) {
    const float* x    = (const float*)d_in[0];
    const float* rel  = (const float*)d_in[1];
    const int*   mask = (const int*)  d_in[2];
    const float* Wq   = (const float*)d_in[3];
    const float* bq   = (const float*)d_in[4];
    const float* Wk   = (const float*)d_in[5];
    const float* bk   = (const float*)d_in[6];
    const float* Wv   = (const float*)d_in[7];
    const float* bv   = (const float*)d_in[8];
    const float* Wo   = (const float*)d_in[9];
    const float* bo   = (const float*)d_in[10];
    float* out = (float*)d_out;

    float *dQ, *dK, *dV, *dCtx;
    cudaGetSymbolAddress((void**)&dQ,   g_Q);
    cudaGetSymbolAddress((void**)&dK,   g_K);
    cudaGetSymbolAddress((void**)&dV,   g_V);
    cudaGetSymbolAddress((void**)&dCtx, g_ctx);

    gemm_qkv<<<dim3(DD / 128, MROWS / 128, 3), 256>>>(
        x, Wq, Wk, Wv, bq, bk, bv, rel, dQ, dK, dV);

    attn_mma<<<dim3(SS / 128, BB * HH), 256>>>(dQ, dK, dV, mask, dCtx);

    gemm_out<<<dim3(DD / 128, MROWS / 128), 256>>>(dCtx, Wo, bo, out);
}

// round 13
// speedup vs baseline: 3.9560x; 1.0115x over previous
#include <cuda_runtime.h>
#include <cuda_fp16.h>
#include <cuda_bf16.h>

// Problem constants
#define BB 8
#define SS 1024
#define DD 1024
#define HH 16
#define HD 64
#define MROWS (BB*SS)     // 8192

// Scratch (device globals; no allocation allowed)
__device__ float g_Q[(size_t)BB*HH*SS*HD];
__device__ float g_K[(size_t)BB*HH*SS*HD];
__device__ float g_V[(size_t)BB*HH*SS*HD];
__device__ float g_ctx[(size_t)BB*SS*DD];

__device__ __forceinline__ unsigned f2tf(float f) {
    unsigned u;
    asm("cvt.rna.tf32.f32 %0, %1;" : "=r"(u) : "f"(f));
    return u;
}

// pack two floats into f16x2 {lo, hi}
__device__ __forceinline__ unsigned pack_h2(float lo, float hi) {
    unsigned u;
    asm("cvt.rn.f16x2.f32 %0, %1, %2;" : "=r"(u) : "f"(hi), "f"(lo));
    return u;
}

__device__ __forceinline__ void mma_tf32(float c[4], const unsigned a[4], const unsigned b[2]) {
    asm volatile(
        "mma.sync.aligned.m16n8k8.row.col.f32.tf32.tf32.f32 "
        "{%0,%1,%2,%3}, {%4,%5,%6,%7}, {%8,%9}, {%0,%1,%2,%3};"
        : "+f"(c[0]), "+f"(c[1]), "+f"(c[2]), "+f"(c[3])
        : "r"(a[0]), "r"(a[1]), "r"(a[2]), "r"(a[3]),
          "r"(b[0]), "r"(b[1]));
}

__device__ __forceinline__ void mma_f16(float c[4], const unsigned a[4], const unsigned b[2]) {
    asm volatile(
        "mma.sync.aligned.m16n8k16.row.col.f32.f16.f16.f32 "
        "{%0,%1,%2,%3}, {%4,%5,%6,%7}, {%8,%9}, {%0,%1,%2,%3};"
        : "+f"(c[0]), "+f"(c[1]), "+f"(c[2]), "+f"(c[3])
        : "r"(a[0]), "r"(a[1]), "r"(a[2]), "r"(a[3]),
          "r"(b[0]), "r"(b[1]));
}

__device__ __forceinline__ void ldsm_x4(unsigned r[4], unsigned addr) {
    asm volatile(
        "ldmatrix.sync.aligned.m8n8.x4.shared.b16 {%0,%1,%2,%3}, [%4];"
        : "=r"(r[0]), "=r"(r[1]), "=r"(r[2]), "=r"(r[3]) : "r"(addr));
}

__device__ __forceinline__ void ldsm_x4_trans(unsigned r[4], unsigned addr) {
    asm volatile(
        "ldmatrix.sync.aligned.m8n8.x4.trans.shared.b16 {%0,%1,%2,%3}, [%4];"
        : "=r"(r[0]), "=r"(r[1]), "=r"(r[2]), "=r"(r[3]) : "r"(addr));
}

// ---------------------------------------------------------------------------
// fp16 GEMM body. Tile BM=BN=128, BK=32; 256 threads = 8 warps (warp 64x32).
// Xs [m][k] halves, stride 40 (80B rows -> conflict-free LDSM + STS.128).
// Ws [k][n] halves, stride 136 (272B rows -> conflict-free LDSM.trans).
// A-frags: ldmatrix.x4; B-frags: ldmatrix.x4.trans; mma m16n8k16 f16->f32.
// Register-prefetch pipeline across k-tiles.
// ---------------------------------------------------------------------------
struct GemmSmem {
    __half Xs[128][40];
    __half Ws[32][136];
};

__device__ __forceinline__ void gemm_body(
    const float* __restrict__ X, const float* __restrict__ W,
    GemmSmem& sm, float acc[4][4][4], int m0, int n0)
{
    const int tid  = threadIdx.x;
    const int lane = tid & 31;
    const int warp = tid >> 5;
    const int wm   = warp & 1;
    const int wn   = warp >> 1;

    // load coordinates
    const int xr = tid >> 1;          // X row 0..127
    const int xc = (tid & 1) * 16;    // X k offset (floats == halves index)
    const int wr = tid >> 3;          // W k-row 0..31
    const int wc = (tid & 7) * 16;    // W n offset

    // ldmatrix base addresses
    unsigned aBase[4], bBase;
    {
        unsigned xs0 = (unsigned)__cvta_generic_to_shared(&sm.Xs[0][0]);
        unsigned ws0 = (unsigned)__cvta_generic_to_shared(&sm.Ws[0][0]);
        #pragma unroll
        for (int mt = 0; mt < 4; mt++) {
            int row = wm * 64 + mt * 16 + (lane & 15);
            aBase[mt] = xs0 + (unsigned)(row * 80 + (lane >> 4) * 16);
        }
        int brow = (lane & 7) + ((lane >> 3) & 1) * 8;
        bBase = ws0 + (unsigned)(brow * 272 + (wn * 32 + (lane >> 4) * 8) * 2);
    }

    float4 px[4], pw[4];
    #pragma unroll
    for (int i = 0; i < 4; i++) {
        px[i] = *(const float4*)(X + (size_t)(m0 + xr) * DD + xc + i * 4);
        pw[i] = *(const float4*)(W + (size_t)wr * DD + n0 + wc + i * 4);
    }

    for (int k0 = 0; k0 < DD; k0 += 32) {
        // convert + store current tile
        {
            uint4 u;
            u.x = pack_h2(px[0].x, px[0].y); u.y = pack_h2(px[0].z, px[0].w);
            u.z = pack_h2(px[1].x, px[1].y); u.w = pack_h2(px[1].z, px[1].w);
            *(uint4*)&sm.Xs[xr][xc] = u;
            u.x = pack_h2(px[2].x, px[2].y); u.y = pack_h2(px[2].z, px[2].w);
            u.z = pack_h2(px[3].x, px[3].y); u.w = pack_h2(px[3].z, px[3].w);
            *(uint4*)&sm.Xs[xr][xc + 8] = u;
            u.x = pack_h2(pw[0].x, pw[0].y); u.y = pack_h2(pw[0].z, pw[0].w);
            u.z = pack_h2(pw[1].x, pw[1].y); u.w = pack_h2(pw[1].z, pw[1].w);
            *(uint4*)&sm.Ws[wr][wc] = u;
            u.x = pack_h2(pw[2].x, pw[2].y); u.y = pack_h2(pw[2].z, pw[2].w);
            u.z = pack_h2(pw[3].x, pw[3].y); u.w = pack_h2(pw[3].z, pw[3].w);
            *(uint4*)&sm.Ws[wr][wc + 8] = u;
        }
        __syncthreads();

        // prefetch next tile (hidden under MMAs)
        if (k0 + 32 < DD) {
            #pragma unroll
            for (int i = 0; i < 4; i++) {
                px[i] = *(const float4*)(X + (size_t)(m0 + xr) * DD + (k0 + 32) + xc + i * 4);
                pw[i] = *(const float4*)(W + (size_t)(k0 + 32 + wr) * DD + n0 + wc + i * 4);
            }
        }

        #pragma unroll
        for (int ks = 0; ks < 2; ks++) {
            unsigned a[4][4], b[4][2];
            #pragma unroll
            for (int mt = 0; mt < 4; mt++)
                ldsm_x4(a[mt], aBase[mt] + (unsigned)(ks * 32));
            {
                unsigned r[4];
                ldsm_x4_trans(r, bBase + (unsigned)(ks * 16 * 272));
                b[0][0] = r[0]; b[0][1] = r[1];
                b[1][0] = r[2]; b[1][1] = r[3];
                ldsm_x4_trans(r, bBase + (unsigned)(ks * 16 * 272 + 32));
                b[2][0] = r[0]; b[2][1] = r[1];
                b[3][0] = r[2]; b[3][1] = r[3];
            }
            #pragma unroll
            for (int mt = 0; mt < 4; mt++)
                #pragma unroll
                for (int nt = 0; nt < 4; nt++)
                    mma_f16(acc[mt][nt], a[mt], b[nt]);
        }
        __syncthreads();
    }
}

// Fused Q/K/V projection: z = blockIdx.z selects weights/bias/epilogue.
__global__ void __launch_bounds__(256, 2) gemm_qkv(
    const float* __restrict__ X,
    const float* __restrict__ Wq, const float* __restrict__ Wk, const float* __restrict__ Wv,
    const float* __restrict__ bq, const float* __restrict__ bk, const float* __restrict__ bv,
    const float* __restrict__ rel,
    float* __restrict__ Qo, float* __restrict__ Ko, float* __restrict__ Vo)
{
    __shared__ GemmSmem sm;

    const int z = blockIdx.z;
    const float* W    = (z == 0) ? Wq : (z == 1) ? Wk : Wv;
    const float* bias = (z == 0) ? bq : (z == 1) ? bk : bv;
    float*       Y    = (z == 0) ? Qo : (z == 1) ? Ko : Vo;

    const int tid  = threadIdx.x;
    const int warp = tid >> 5;
    const int lane = tid & 31;
    const int g    = lane >> 2;
    const int t4   = lane & 3;
    const int wm   = warp & 1;
    const int wn   = warp >> 1;
    const int m0   = blockIdx.y * 128;
    const int n0   = blockIdx.x * 128;

    float acc[4][4][4];
    #pragma unroll
    for (int mt = 0; mt < 4; mt++)
        #pragma unroll
        for (int nt = 0; nt < 4; nt++)
            #pragma unroll
            for (int r = 0; r < 4; r++) acc[mt][nt][r] = 0.f;

    gemm_body(X, W, sm, acc, m0, n0);

    const float scale = 0.125f;   // HD^-0.5
    #pragma unroll
    for (int mt = 0; mt < 4; mt++) {
        #pragma unroll
        for (int nt = 0; nt < 4; nt++) {
            int row0 = m0 + wm * 64 + mt * 16 + g;
            int col0 = n0 + wn * 32 + nt * 8 + t4 * 2;
            #pragma unroll
            for (int r = 0; r < 4; r++) {
                int row = row0 + (r >> 1) * 8;
                int col = col0 + (r & 1);
                float y = acc[mt][nt][r] + bias[col];
                int b_  = row >> 10;
                int s   = row & 1023;
                int h   = col >> 6;
                int hd  = col & 63;
                size_t idx = (((size_t)(b_ * HH + h) * SS) + s) * HD + hd;
                if (z == 1) y = y * scale + rel[s * HD + hd];
                Y[idx] = y;
            }
        }
    }
}

// Output projection: Y[M,N] = X @ Wo + bo (plain store).
__global__ void __launch_bounds__(256, 2) gemm_out(
    const float* __restrict__ X, const float* __restrict__ W,
    const float* __restrict__ bias, float* __restrict__ Y)
{
    __shared__ GemmSmem sm;

    const int tid  = threadIdx.x;
    const int warp = tid >> 5;
    const int lane = tid & 31;
    const int g    = lane >> 2;
    const int t4   = lane & 3;
    const int wm   = warp & 1;
    const int wn   = warp >> 1;
    const int m0   = blockIdx.y * 128;
    const int n0   = blockIdx.x * 128;

    float acc[4][4][4];
    #pragma unroll
    for (int mt = 0; mt < 4; mt++)
        #pragma unroll
        for (int nt = 0; nt < 4; nt++)
            #pragma unroll
            for (int r = 0; r < 4; r++) acc[mt][nt][r] = 0.f;

    gemm_body(X, W, sm, acc, m0, n0);

    #pragma unroll
    for (int mt = 0; mt < 4; mt++) {
        #pragma unroll
        for (int nt = 0; nt < 4; nt++) {
            int row0 = m0 + wm * 64 + mt * 16 + g;
            int col0 = n0 + wn * 32 + nt * 8 + t4 * 2;
            #pragma unroll
            for (int r = 0; r < 4; r++) {
                int row = row0 + (r >> 1) * 8;
                int col = col0 + (r & 1);
                Y[(size_t)row * DD + col] = acc[mt][nt][r] + bias[col];
            }
        }
    }
}

// ---------------------------------------------------------------------------
// Flash attention with tf32 tensor cores (unchanged).
// ---------------------------------------------------------------------------
struct AttnSmem {
    union {
        unsigned q[128][68];
        struct {
            unsigned k[64][68];
            unsigned v[64][72];
        } kv;
    } u;
    float mbias[64];
};

__global__ void __launch_bounds__(256, 2) attn_mma(
    const float* __restrict__ Q, const float* __restrict__ Kp,
    const float* __restrict__ V, const int* __restrict__ mask,
    float* __restrict__ ctx)
{
    __shared__ AttnSmem sm;

    const int tid  = threadIdx.x;
    const int warp = tid >> 5;
    const int lane = tid & 31;
    const int g    = lane >> 2;
    const int t4   = lane & 3;
    const int bh   = blockIdx.y;
    const int b    = bh >> 4;
    const int h    = bh & 15;
    const int s0   = blockIdx.x << 7;

    const float* Qb = Q  + (size_t)bh * SS * HD;
    const float* Kb = Kp + (size_t)bh * SS * HD;
    const float* Vb = V  + (size_t)bh * SS * HD;
    const int*   mb = mask + b * SS;

    #pragma unroll
    for (int i = 0; i < 8; i++) {
        int idx = tid + i * 256;
        int row = idx >> 4;
        int c   = idx & 15;
        float4 v = *(const float4*)(Qb + (size_t)(s0 + row) * HD + c * 4);
        sm.u.q[row][c*4+0] = f2tf(v.x);
        sm.u.q[row][c*4+1] = f2tf(v.y);
        sm.u.q[row][c*4+2] = f2tf(v.z);
        sm.u.q[row][c*4+3] = f2tf(v.w);
    }
    __syncthreads();

    unsigned Qa[8][4];
    {
        const int mr = warp * 16;
        #pragma unroll
        for (int kt = 0; kt < 8; kt++) {
            Qa[kt][0] = sm.u.q[mr + g    ][kt*8 + t4];
            Qa[kt][1] = sm.u.q[mr + g + 8][kt*8 + t4];
            Qa[kt][2] = sm.u.q[mr + g    ][kt*8 + t4 + 4];
            Qa[kt][3] = sm.u.q[mr + g + 8][kt*8 + t4 + 4];
        }
    }
    __syncthreads();

    float Oc[8][4];
    #pragma unroll
    for (int nt = 0; nt < 8; nt++)
        #pragma unroll
        for (int r = 0; r < 4; r++) Oc[nt][r] = 0.f;
    float m0r = -1e30f, m1r = -1e30f, l0r = 0.f, l1r = 0.f;

    const int src0 = (lane & ~3) | (t4 >> 1);
    const int src2 = (lane & ~3) | ((t4 >> 1) + 2);
    const bool selodd = (t4 & 1);

    for (int t0 = 0; t0 < SS; t0 += 64) {
        #pragma unroll
        for (int i = 0; i < 4; i++) {
            int idx = tid + i * 256;
            int row = idx >> 4;
            int c   = idx & 15;
            float4 kv = *(const float4*)(Kb + (size_t)(t0 + row) * HD + c * 4);
            sm.u.kv.k[row][c*4+0] = f2tf(kv.x);
            sm.u.kv.k[row][c*4+1] = f2tf(kv.y);
            sm.u.kv.k[row][c*4+2] = f2tf(kv.z);
            sm.u.kv.k[row][c*4+3] = f2tf(kv.w);
            float4 vv = *(const float4*)(Vb + (size_t)(t0 + row) * HD + c * 4);
            sm.u.kv.v[row][c*4+0] = f2tf(vv.x);
            sm.u.kv.v[row][c*4+1] = f2tf(vv.y);
            sm.u.kv.v[row][c*4+2] = f2tf(vv.z);
            sm.u.kv.v[row][c*4+3] = f2tf(vv.w);
        }
        if (tid < 64) sm.mbias[tid] = (mb[t0 + tid] == 0) ? -1e30f : 0.f;
        __syncthreads();

        float s[8][4];
        #pragma unroll
        for (int nt = 0; nt < 8; nt++) {
            s[nt][0] = s[nt][1] = s[nt][2] = s[nt][3] = 0.f;
            #pragma unroll
            for (int kt = 0; kt < 8; kt++) {
                unsigned bf[2];
                bf[0] = sm.u.kv.k[nt*8 + g][kt*8 + t4];
                bf[1] = sm.u.kv.k[nt*8 + g][kt*8 + t4 + 4];
                mma_tf32(s[nt], Qa[kt], bf);
            }
            float mb0 = sm.mbias[nt*8 + 2*t4];
            float mb1 = sm.mbias[nt*8 + 2*t4 + 1];
            s[nt][0] += mb0; s[nt][1] += mb1;
            s[nt][2] += mb0; s[nt][3] += mb1;
        }

        float mx0 = -1e30f, mx1 = -1e30f;
        #pragma unroll
        for (int nt = 0; nt < 8; nt++) {
            mx0 = fmaxf(mx0, fmaxf(s[nt][0], s[nt][1]));
            mx1 = fmaxf(mx1, fmaxf(s[nt][2], s[nt][3]));
        }
        mx0 = fmaxf(mx0, __shfl_xor_sync(0xffffffffu, mx0, 1));
        mx0 = fmaxf(mx0, __shfl_xor_sync(0xffffffffu, mx0, 2));
        mx1 = fmaxf(mx1, __shfl_xor_sync(0xffffffffu, mx1, 1));
        mx1 = fmaxf(mx1, __shfl_xor_sync(0xffffffffu, mx1, 2));

        float nm0 = fmaxf(m0r, mx0);
        float nm1 = fmaxf(m1r, mx1);
        float al0 = __expf(m0r - nm0);
        float al1 = __expf(m1r - nm1);
        m0r = nm0; m1r = nm1;

        unsigned pu[8][4];
        float rs0 = 0.f, rs1 = 0.f;
        #pragma unroll
        for (int nt = 0; nt < 8; nt++) {
            float p0 = __expf(s[nt][0] - nm0);
            float p1 = __expf(s[nt][1] - nm0);
            float p2 = __expf(s[nt][2] - nm1);
            float p3 = __expf(s[nt][3] - nm1);
            rs0 += p0 + p1;
            rs1 += p2 + p3;
            pu[nt][0] = f2tf(p0);
            pu[nt][1] = f2tf(p1);
            pu[nt][2] = f2tf(p2);
            pu[nt][3] = f2tf(p3);
        }
        rs0 += __shfl_xor_sync(0xffffffffu, rs0, 1);
        rs0 += __shfl_xor_sync(0xffffffffu, rs0, 2);
        rs1 += __shfl_xor_sync(0xffffffffu, rs1, 1);
        rs1 += __shfl_xor_sync(0xffffffffu, rs1, 2);
        l0r = l0r * al0 + rs0;
        l1r = l1r * al1 + rs1;

        #pragma unroll
        for (int nt = 0; nt < 8; nt++) {
            Oc[nt][0] *= al0; Oc[nt][1] *= al0;
            Oc[nt][2] *= al1; Oc[nt][3] *= al1;
        }

        #pragma unroll
        for (int kt = 0; kt < 8; kt++) {
            unsigned aP[4];
            unsigned v00 = __shfl_sync(0xffffffffu, pu[kt][0], src0);
            unsigned v01 = __shfl_sync(0xffffffffu, pu[kt][1], src0);
            unsigned v20 = __shfl_sync(0xffffffffu, pu[kt][2], src0);
            unsigned v21 = __shfl_sync(0xffffffffu, pu[kt][3], src0);
            unsigned w00 = __shfl_sync(0xffffffffu, pu[kt][0], src2);
            unsigned w01 = __shfl_sync(0xffffffffu, pu[kt][1], src2);
            unsigned w20 = __shfl_sync(0xffffffffu, pu[kt][2], src2);
            unsigned w21 = __shfl_sync(0xffffffffu, pu[kt][3], src2);
            aP[0] = selodd ? v01 : v00;
            aP[1] = selodd ? v21 : v20;
            aP[2] = selodd ? w01 : w00;
            aP[3] = selodd ? w21 : w20;
            #pragma unroll
            for (int nt = 0; nt < 8; nt++) {
                unsigned bf[2];
                bf[0] = sm.u.kv.v[kt*8 + t4    ][nt*8 + g];
                bf[1] = sm.u.kv.v[kt*8 + t4 + 4][nt*8 + g];
                mma_tf32(Oc[nt], aP, bf);
            }
        }
        __syncthreads();
    }

    const float inv0 = 1.0f / l0r;
    const float inv1 = 1.0f / l1r;
    const int r0 = s0 + warp * 16 + g;
    #pragma unroll
    for (int nt = 0; nt < 8; nt++) {
        int col = h * 64 + nt * 8 + 2 * t4;
        float2 o0 = make_float2(Oc[nt][0] * inv0, Oc[nt][1] * inv0);
        float2 o1 = make_float2(Oc[nt][2] * inv1, Oc[nt][3] * inv1);
        *(float2*)(ctx + ((size_t)b * SS + r0    ) * DD + col) = o0;
        *(float2*)(ctx + ((size_t)b * SS + r0 + 8) * DD + col) = o1;
    }
}

// ---------------------------------------------------------------------------

extern "C" void kernel_launch(void* const* d_in, const int* in_sizes, int n_in,
                              void* d_out, int out_size) {
    const float* x    = (const float*)d_in[0];
    const float* rel  = (const float*)d_in[1];
    const int*   mask = (const int*)  d_in[2];
    const float* Wq   = (const float*)d_in[3];
    const float* bq   = (const float*)d_in[4];
    const float* Wk   = (const float*)d_in[5];
    const float* bk   = (const float*)d_in[6];
    const float* Wv   = (const float*)d_in[7];
    const float* bv   = (const float*)d_in[8];
    const float* Wo   = (const float*)d_in[9];
    const float* bo   = (const float*)d_in[10];
    float* out = (float*)d_out;

    float *dQ, *dK, *dV, *dCtx;
    cudaGetSymbolAddress((void**)&dQ,   g_Q);
    cudaGetSymbolAddress((void**)&dK,   g_K);
    cudaGetSymbolAddress((void**)&dV,   g_V);
    cudaGetSymbolAddress((void**)&dCtx, g_ctx);

    gemm_qkv<<<dim3(DD / 128, MROWS / 128, 3), 256>>>(
        x, Wq, Wk, Wv, bq, bk, bv, rel, dQ, dK, dV);

    attn_mma<<<dim3(SS / 128, BB * HH), 256>>>(dQ, dK, dV, mask, dCtx);

    gemm_out<<<dim3(DD / 128, MROWS / 128), 256>>>(dCtx, Wo, bo, out);
}